// round 1
// baseline (speedup 1.0000x reference)
#include <cuda_runtime.h>
#include <math.h>

#define Bn 2
#define Sn 2048
#define Dn 1024
#define Hn 16
#define HDn 64
#define BSn (Bn*Sn)      // 4096
#define N3D (3*Dn)       // 3072

// Scratch (device globals — no allocation in kernel_launch)
__device__ float g_q[Bn*Hn*Sn*HDn];
__device__ float g_k[Bn*Hn*Sn*HDn];
__device__ float g_v[Bn*Hn*Sn*HDn];
__device__ float g_att[Bn*Hn*Sn*HDn];

// ---------------------------------------------------------------------------
// Kernel 1: QKV projection. C[4096,3072] = hs[4096,1024] @ w_attn[1024,3072]+b
// 128x128x8 tiles, 256 threads, 8x8 per thread. Epilogue scatters into
// per-head layout g_q/g_k/g_v [B,H,S,HD].
// ---------------------------------------------------------------------------
__global__ __launch_bounds__(256) void qkv_gemm(const float* __restrict__ A,
                                                const float* __restrict__ W,
                                                const float* __restrict__ bias) {
    const int K = 1024, N = N3D;
    __shared__ __align__(16) float As[8][128];
    __shared__ __align__(16) float Bs[8][128];
    int tid = threadIdx.x;
    int tx = tid & 15, ty = tid >> 4;
    int row0 = blockIdx.y * 128;
    int col0 = blockIdx.x * 128;
    int ar = tid >> 1;            // 0..127
    int ac4 = (tid & 1) * 4;      // 0 or 4
    int br = tid >> 5;            // 0..7
    int bc4 = (tid & 31) * 4;
    float acc[8][8] = {};
    for (int k0 = 0; k0 < K; k0 += 8) {
        float4 av = *(const float4*)&A[(size_t)(row0 + ar) * K + k0 + ac4];
        As[ac4 + 0][ar] = av.x; As[ac4 + 1][ar] = av.y;
        As[ac4 + 2][ar] = av.z; As[ac4 + 3][ar] = av.w;
        *(float4*)&Bs[br][bc4] = *(const float4*)&W[(size_t)(k0 + br) * N + col0 + bc4];
        __syncthreads();
        #pragma unroll
        for (int kk = 0; kk < 8; kk++) {
            float4 a0 = *(const float4*)&As[kk][ty * 8];
            float4 a1 = *(const float4*)&As[kk][ty * 8 + 4];
            float4 b0 = *(const float4*)&Bs[kk][tx * 8];
            float4 b1 = *(const float4*)&Bs[kk][tx * 8 + 4];
            float ra[8] = {a0.x, a0.y, a0.z, a0.w, a1.x, a1.y, a1.z, a1.w};
            float rb[8] = {b0.x, b0.y, b0.z, b0.w, b1.x, b1.y, b1.z, b1.w};
            #pragma unroll
            for (int i = 0; i < 8; i++)
                #pragma unroll
                for (int j = 0; j < 8; j++)
                    acc[i][j] = fmaf(ra[i], rb[j], acc[i][j]);
        }
        __syncthreads();
    }
    #pragma unroll
    for (int i = 0; i < 8; i++) {
        int r = row0 + ty * 8 + i;
        int b = r >> 11;       // / 2048
        int s = r & 2047;
        #pragma unroll
        for (int j = 0; j < 8; j++) {
            int c = col0 + tx * 8 + j;
            float v = acc[i][j] + bias[c];
            int which = c >> 10;          // 0:q 1:k 2:v
            int dcol = c & 1023;
            int h = dcol >> 6;
            int hd = dcol & 63;
            float* dst = (which == 0) ? g_q : (which == 1) ? g_k : g_v;
            dst[(size_t)(((b * Hn) + h) * Sn + s) * HDn + hd] = v;
        }
    }
}

// ---------------------------------------------------------------------------
// Kernel 2: raw attention scores (lower-triangle 128x128 blocks only).
// score[q,k] = dot(q_row,k_row)/8 + attention_mask[b,k]. Upper-triangle blocks
// skipped; in-block masked entries left as raw scores (softmax ignores them).
// ---------------------------------------------------------------------------
__global__ __launch_bounds__(256) void scores_kernel(const float* __restrict__ mask,
                                                     float* __restrict__ Wout) {
    int kb = blockIdx.x, qb = blockIdx.y, bh = blockIdx.z;
    if (kb > qb) return;
    const float* qp = g_q + (size_t)bh * Sn * HDn;
    const float* kp = g_k + (size_t)bh * Sn * HDn;
    int b = bh / Hn;
    __shared__ __align__(16) float Qs[8][128];
    __shared__ __align__(16) float Ks[8][128];
    int tid = threadIdx.x;
    int tx = tid & 15, ty = tid >> 4;
    int ar = tid >> 1;
    int ac4 = (tid & 1) * 4;
    int row0 = qb * 128, col0 = kb * 128;
    float acc[8][8] = {};
    for (int k0 = 0; k0 < HDn; k0 += 8) {
        float4 qv = *(const float4*)&qp[(size_t)(row0 + ar) * HDn + k0 + ac4];
        Qs[ac4 + 0][ar] = qv.x; Qs[ac4 + 1][ar] = qv.y;
        Qs[ac4 + 2][ar] = qv.z; Qs[ac4 + 3][ar] = qv.w;
        float4 kv = *(const float4*)&kp[(size_t)(col0 + ar) * HDn + k0 + ac4];
        Ks[ac4 + 0][ar] = kv.x; Ks[ac4 + 1][ar] = kv.y;
        Ks[ac4 + 2][ar] = kv.z; Ks[ac4 + 3][ar] = kv.w;
        __syncthreads();
        #pragma unroll
        for (int kk = 0; kk < 8; kk++) {
            float4 a0 = *(const float4*)&Qs[kk][ty * 8];
            float4 a1 = *(const float4*)&Qs[kk][ty * 8 + 4];
            float4 b0 = *(const float4*)&Ks[kk][tx * 8];
            float4 b1 = *(const float4*)&Ks[kk][tx * 8 + 4];
            float ra[8] = {a0.x, a0.y, a0.z, a0.w, a1.x, a1.y, a1.z, a1.w};
            float rb[8] = {b0.x, b0.y, b0.z, b0.w, b1.x, b1.y, b1.z, b1.w};
            #pragma unroll
            for (int i = 0; i < 8; i++)
                #pragma unroll
                for (int j = 0; j < 8; j++)
                    acc[i][j] = fmaf(ra[i], rb[j], acc[i][j]);
        }
        __syncthreads();
    }
    const float scale = 0.125f;  // 1/sqrt(64)
    #pragma unroll
    for (int i = 0; i < 8; i++) {
        int qr = row0 + ty * 8 + i;
        #pragma unroll
        for (int j = 0; j < 8; j++) {
            int kc = col0 + tx * 8 + j;
            Wout[((size_t)bh * Sn + qr) * Sn + kc] = acc[i][j] * scale + mask[b * Sn + kc];
        }
    }
}

// ---------------------------------------------------------------------------
// Kernel 3: row softmax. One block per (b,h,q) row. Reads the valid prefix
// (k <= q) into smem, computes max & sum(exp), writes normalized weights and
// exact zeros for the masked suffix (matches fp32 exp(-10000-max) underflow).
// ---------------------------------------------------------------------------
__global__ __launch_bounds__(256) void softmax_kernel(float* __restrict__ Wm) {
    __shared__ float buf[Sn];
    __shared__ float red[8];
    int row = blockIdx.x;            // 0 .. B*H*S-1
    int q = row & (Sn - 1);
    int len = q + 1;
    float* wrow = Wm + (size_t)row * Sn;
    int tid = threadIdx.x;
    int lane = tid & 31, warp = tid >> 5;

    float mx = -1e30f;
    for (int c = tid; c < len; c += 256) {
        float v = wrow[c];
        buf[c] = v;
        mx = fmaxf(mx, v);
    }
    #pragma unroll
    for (int o = 16; o > 0; o >>= 1) mx = fmaxf(mx, __shfl_xor_sync(0xffffffffu, mx, o));
    if (lane == 0) red[warp] = mx;
    __syncthreads();
    if (tid < 32) {
        float t = (tid < 8) ? red[tid] : -1e30f;
        #pragma unroll
        for (int o = 4; o > 0; o >>= 1) t = fmaxf(t, __shfl_xor_sync(0xffffffffu, t, o));
        if (tid == 0) red[0] = t;
    }
    __syncthreads();
    mx = red[0];
    __syncthreads();

    float sum = 0.0f;
    for (int c = tid; c < len; c += 256) {
        float e = __expf(buf[c] - mx);
        buf[c] = e;
        sum += e;
    }
    #pragma unroll
    for (int o = 16; o > 0; o >>= 1) sum += __shfl_xor_sync(0xffffffffu, sum, o);
    if (lane == 0) red[warp] = sum;
    __syncthreads();
    if (tid < 32) {
        float t = (tid < 8) ? red[tid] : 0.0f;
        #pragma unroll
        for (int o = 4; o > 0; o >>= 1) t += __shfl_xor_sync(0xffffffffu, t, o);
        if (tid == 0) red[0] = t;
    }
    __syncthreads();
    float inv = 1.0f / red[0];

    for (int c = tid; c < Sn; c += 256) {
        wrow[c] = (c < len) ? buf[c] * inv : 0.0f;
    }
}

// ---------------------------------------------------------------------------
// Kernel 4: attn_output_heads = weights @ v per (b,h). 128 q-rows x 64 cols
// per block, 256 threads, 8x4 per thread. Only iterates k-blocks <= q-block
// (upper-triangle weights are exact zeros, so the diagonal block needs no mask).
// ---------------------------------------------------------------------------
__global__ __launch_bounds__(256) void av_kernel(const float* __restrict__ Wm) {
    int qb = blockIdx.x, bh = blockIdx.y;
    const float* wrow = Wm + (size_t)bh * Sn * Sn;
    const float* vp = g_v + (size_t)bh * Sn * HDn;
    __shared__ __align__(16) float Ws[16][128];
    __shared__ __align__(16) float Vs[16][68];
    int tid = threadIdx.x;
    int tx = tid & 15, ty = tid >> 4;
    int row0 = qb * 128;
    int kend = row0 + 128;
    float acc[8][4] = {};
    for (int k0 = 0; k0 < kend; k0 += 16) {
        #pragma unroll
        for (int it = 0; it < 2; it++) {
            int fidx = tid + it * 256;
            int r = fidx >> 2, c4 = (fidx & 3) * 4;
            float4 wv = *(const float4*)&wrow[(size_t)(row0 + r) * Sn + k0 + c4];
            Ws[c4 + 0][r] = wv.x; Ws[c4 + 1][r] = wv.y;
            Ws[c4 + 2][r] = wv.z; Ws[c4 + 3][r] = wv.w;
        }
        {
            int r = tid >> 4, c4 = (tid & 15) * 4;
            *(float4*)&Vs[r][c4] = *(const float4*)&vp[(size_t)(k0 + r) * HDn + c4];
        }
        __syncthreads();
        #pragma unroll
        for (int kk = 0; kk < 16; kk++) {
            float4 w0 = *(const float4*)&Ws[kk][ty * 8];
            float4 w1 = *(const float4*)&Ws[kk][ty * 8 + 4];
            float4 v0 = *(const float4*)&Vs[kk][tx * 4];
            float rw[8] = {w0.x, w0.y, w0.z, w0.w, w1.x, w1.y, w1.z, w1.w};
            float rv[4] = {v0.x, v0.y, v0.z, v0.w};
            #pragma unroll
            for (int i = 0; i < 8; i++)
                #pragma unroll
                for (int j = 0; j < 4; j++)
                    acc[i][j] = fmaf(rw[i], rv[j], acc[i][j]);
        }
        __syncthreads();
    }
    #pragma unroll
    for (int i = 0; i < 8; i++)
        #pragma unroll
        for (int j = 0; j < 4; j++)
            g_att[((size_t)bh * Sn + row0 + ty * 8 + i) * HDn + tx * 4 + j] = acc[i][j];
}

// ---------------------------------------------------------------------------
// Kernel 5: output projection. A[r,c] = g_att head-transposed on the fly.
// out[4096,1024] = A @ w_proj + b_proj, written to d_out[0 .. B*S*D).
// ---------------------------------------------------------------------------
__global__ __launch_bounds__(256) void proj_gemm(const float* __restrict__ W,
                                                 const float* __restrict__ bias,
                                                 float* __restrict__ out) {
    const int K = 1024, N = 1024;
    __shared__ __align__(16) float As[8][128];
    __shared__ __align__(16) float Bs[8][128];
    int tid = threadIdx.x;
    int tx = tid & 15, ty = tid >> 4;
    int row0 = blockIdx.y * 128;
    int col0 = blockIdx.x * 128;
    int ar = tid >> 1;
    int ac4 = (tid & 1) * 4;
    int br = tid >> 5;
    int bc4 = (tid & 31) * 4;
    float acc[8][8] = {};
    for (int k0 = 0; k0 < K; k0 += 8) {
        int r = row0 + ar;
        int b = r >> 11, s = r & 2047;
        int c = k0 + ac4;                 // 4-aligned -> same head for 4 elems
        float4 av = *(const float4*)&g_att[(((size_t)b * Hn + (c >> 6)) * Sn + s) * HDn + (c & 63)];
        As[ac4 + 0][ar] = av.x; As[ac4 + 1][ar] = av.y;
        As[ac4 + 2][ar] = av.z; As[ac4 + 3][ar] = av.w;
        *(float4*)&Bs[br][bc4] = *(const float4*)&W[(size_t)(k0 + br) * N + col0 + bc4];
        __syncthreads();
        #pragma unroll
        for (int kk = 0; kk < 8; kk++) {
            float4 a0 = *(const float4*)&As[kk][ty * 8];
            float4 a1 = *(const float4*)&As[kk][ty * 8 + 4];
            float4 b0 = *(const float4*)&Bs[kk][tx * 8];
            float4 b1 = *(const float4*)&Bs[kk][tx * 8 + 4];
            float ra[8] = {a0.x, a0.y, a0.z, a0.w, a1.x, a1.y, a1.z, a1.w};
            float rb[8] = {b0.x, b0.y, b0.z, b0.w, b1.x, b1.y, b1.z, b1.w};
            #pragma unroll
            for (int i = 0; i < 8; i++)
                #pragma unroll
                for (int j = 0; j < 8; j++)
                    acc[i][j] = fmaf(ra[i], rb[j], acc[i][j]);
        }
        __syncthreads();
    }
    #pragma unroll
    for (int i = 0; i < 8; i++) {
        int r = row0 + ty * 8 + i;
        #pragma unroll
        for (int j = 0; j < 8; j++) {
            int c = col0 + tx * 8 + j;
            out[(size_t)r * N + c] = acc[i][j] + bias[c];
        }
    }
}

// ---------------------------------------------------------------------------
extern "C" void kernel_launch(void* const* d_in, const int* in_sizes, int n_in,
                              void* d_out, int out_size) {
    (void)in_sizes; (void)n_in; (void)out_size;
    const float* hs     = (const float*)d_in[0];
    const float* mask   = (const float*)d_in[1];
    const float* w_attn = (const float*)d_in[2];
    const float* b_attn = (const float*)d_in[3];
    const float* w_proj = (const float*)d_in[4];
    const float* b_proj = (const float*)d_in[5];

    float* attn_out = (float*)d_out;                          // [B,S,D]
    float* weights  = (float*)d_out + (size_t)Bn * Sn * Dn;   // [B,H,S,S]

    qkv_gemm<<<dim3(N3D / 128, BSn / 128), 256>>>(hs, w_attn, b_attn);
    scores_kernel<<<dim3(Sn / 128, Sn / 128, Bn * Hn), 256>>>(mask, weights);
    softmax_kernel<<<dim3(Bn * Hn * Sn), 256>>>(weights);
    av_kernel<<<dim3(Sn / 128, Bn * Hn), 256>>>(weights);
    proj_gemm<<<dim3(Dn / 128, BSn / 128), 256>>>(w_proj, b_proj, attn_out);
}

// round 2
// speedup vs baseline: 1.1891x; 1.1891x over previous
#include <cuda_runtime.h>
#include <math.h>

#define Bn 2
#define Sn 2048
#define Dn 1024
#define Hn 16
#define HDn 64
#define BSn (Bn*Sn)      // 4096
#define N3D (3*Dn)       // 3072

// Scratch (device globals — no allocation in kernel_launch)
__device__ float g_q[Bn*Hn*Sn*HDn];
__device__ float g_k[Bn*Hn*Sn*HDn];
__device__ float g_v[Bn*Hn*Sn*HDn];
__device__ float g_att[Bn*Hn*Sn*HDn];

// packed dual-fp32 FMA (Blackwell f32x2): d = a*b + d, lanes independent
#define FMA2(d, a, b) asm("fma.rn.f32x2 %0, %1, %2, %0;" : "+l"(d) : "l"(a), "l"(b))
#define SPLAT2(d, f)  asm("mov.b64 %0, {%1, %1};" : "=l"(d) : "r"(__float_as_uint(f)))
#define UNPK2(lo, hi, p) asm("mov.b64 {%0, %1}, %2;" : "=r"(lo), "=r"(hi) : "l"(p))

// ---------------------------------------------------------------------------
// Kernel 1: QKV projection. C[4096,3072] = hs[4096,1024] @ w_attn[1024,3072]+b
// 128x128 tile, kt=8, double-buffered, FFMA2 inner (col-paired accumulators).
// Epilogue scatters into per-head layout g_q/g_k/g_v [B,H,S,HD].
// ---------------------------------------------------------------------------
__global__ __launch_bounds__(256) void qkv_gemm(const float* __restrict__ A,
                                                const float* __restrict__ W,
                                                const float* __restrict__ bias) {
    const int K = 1024, N = N3D;
    __shared__ __align__(16) float As[2][8][132];
    __shared__ __align__(16) float Bs[2][8][132];
    int tid = threadIdx.x;
    int tx = tid & 15, ty = tid >> 4;
    int row0 = blockIdx.y * 128, col0 = blockIdx.x * 128;
    int ar = tid >> 1, ac4 = (tid & 1) * 4;
    int br = tid >> 5, bc4 = (tid & 31) * 4;
    const float* Aptr = A + (size_t)(row0 + ar) * K + ac4;
    const float* Bptr = W + (size_t)br * N + col0 + bc4;

    // prologue: stage 0
    {
        float4 av = *(const float4*)Aptr;
        float4 bv = *(const float4*)Bptr;
        As[0][ac4 + 0][ar] = av.x; As[0][ac4 + 1][ar] = av.y;
        As[0][ac4 + 2][ar] = av.z; As[0][ac4 + 3][ar] = av.w;
        *(float4*)&Bs[0][br][bc4] = bv;
    }
    __syncthreads();

    unsigned long long acc[8][4];
    #pragma unroll
    for (int i = 0; i < 8; i++)
        #pragma unroll
        for (int j = 0; j < 4; j++) acc[i][j] = 0ull;

    const int T = K / 8;
    for (int t = 0; t < T; t++) {
        int buf = t & 1;
        float4 na, nb;
        if (t + 1 < T) {
            na = *(const float4*)(Aptr + (t + 1) * 8);
            nb = *(const float4*)(Bptr + (size_t)(t + 1) * 8 * N);
        }
        #pragma unroll
        for (int kk = 0; kk < 8; kk++) {
            float4 a0 = *(const float4*)&As[buf][kk][ty * 8];
            float4 a1 = *(const float4*)&As[buf][kk][ty * 8 + 4];
            ulonglong2 b0 = *(const ulonglong2*)&Bs[buf][kk][tx * 8];
            ulonglong2 b1 = *(const ulonglong2*)&Bs[buf][kk][tx * 8 + 4];
            unsigned long long bp[4] = {b0.x, b0.y, b1.x, b1.y};
            float ra[8] = {a0.x, a0.y, a0.z, a0.w, a1.x, a1.y, a1.z, a1.w};
            #pragma unroll
            for (int i = 0; i < 8; i++) {
                unsigned long long ap; SPLAT2(ap, ra[i]);
                #pragma unroll
                for (int j = 0; j < 4; j++) FMA2(acc[i][j], ap, bp[j]);
            }
        }
        if (t + 1 < T) {
            int nbuf = buf ^ 1;
            As[nbuf][ac4 + 0][ar] = na.x; As[nbuf][ac4 + 1][ar] = na.y;
            As[nbuf][ac4 + 2][ar] = na.z; As[nbuf][ac4 + 3][ar] = na.w;
            *(float4*)&Bs[nbuf][br][bc4] = nb;
        }
        __syncthreads();
    }

    #pragma unroll
    for (int i = 0; i < 8; i++) {
        int r = row0 + ty * 8 + i;
        int b = r >> 11;
        int s = r & 2047;
        #pragma unroll
        for (int j = 0; j < 4; j++) {
            unsigned lo, hi; UNPK2(lo, hi, acc[i][j]);
            int c0 = col0 + tx * 8 + 2 * j;
            float v0 = __uint_as_float(lo) + bias[c0];
            float v1 = __uint_as_float(hi) + bias[c0 + 1];
            #pragma unroll
            for (int e = 0; e < 2; e++) {
                int c = c0 + e;
                float v = e ? v1 : v0;
                int which = c >> 10;
                int dcol = c & 1023;
                int h = dcol >> 6, hd = dcol & 63;
                float* dst = (which == 0) ? g_q : (which == 1) ? g_k : g_v;
                dst[(size_t)(((b * Hn) + h) * Sn + s) * HDn + hd] = v;
            }
        }
    }
}

// ---------------------------------------------------------------------------
// Kernel 2: raw attention scores, lower-triangle blocks only (triangular grid).
// score[q,k] = dot(q,k)/8 + mask[b,k]. 128x128 tile, K=64, kt=8, DB, FFMA2.
// ---------------------------------------------------------------------------
__global__ __launch_bounds__(256) void scores_kernel(const float* __restrict__ mask,
                                                     float* __restrict__ Wout) {
    int idx = blockIdx.x;                  // 0..135 lower-tri block pairs
    int qb = (int)((sqrtf(8.0f * idx + 1.0f) - 1.0f) * 0.5f);
    while ((qb + 1) * (qb + 2) / 2 <= idx) qb++;
    while (qb * (qb + 1) / 2 > idx) qb--;
    int kb = idx - qb * (qb + 1) / 2;
    int bh = blockIdx.y;
    const float* qp = g_q + (size_t)bh * Sn * HDn;
    const float* kp = g_k + (size_t)bh * Sn * HDn;
    int b = bh / Hn;
    __shared__ __align__(16) float Qs[2][8][132];
    __shared__ __align__(16) float Ks[2][8][132];
    int tid = threadIdx.x;
    int tx = tid & 15, ty = tid >> 4;
    int ar = tid >> 1, ac4 = (tid & 1) * 4;
    int row0 = qb * 128, col0 = kb * 128;
    const float* Qptr = qp + (size_t)(row0 + ar) * HDn + ac4;
    const float* Kptr = kp + (size_t)(col0 + ar) * HDn + ac4;
    {
        float4 qv = *(const float4*)Qptr;
        float4 kv = *(const float4*)Kptr;
        Qs[0][ac4 + 0][ar] = qv.x; Qs[0][ac4 + 1][ar] = qv.y;
        Qs[0][ac4 + 2][ar] = qv.z; Qs[0][ac4 + 3][ar] = qv.w;
        Ks[0][ac4 + 0][ar] = kv.x; Ks[0][ac4 + 1][ar] = kv.y;
        Ks[0][ac4 + 2][ar] = kv.z; Ks[0][ac4 + 3][ar] = kv.w;
    }
    __syncthreads();

    unsigned long long acc[8][4];
    #pragma unroll
    for (int i = 0; i < 8; i++)
        #pragma unroll
        for (int j = 0; j < 4; j++) acc[i][j] = 0ull;

    const int T = HDn / 8;  // 8
    for (int t = 0; t < T; t++) {
        int buf = t & 1;
        float4 nq, nk;
        if (t + 1 < T) {
            nq = *(const float4*)(Qptr + (t + 1) * 8);
            nk = *(const float4*)(Kptr + (t + 1) * 8);
        }
        #pragma unroll
        for (int kk = 0; kk < 8; kk++) {
            float4 a0 = *(const float4*)&Qs[buf][kk][ty * 8];
            float4 a1 = *(const float4*)&Qs[buf][kk][ty * 8 + 4];
            ulonglong2 b0 = *(const ulonglong2*)&Ks[buf][kk][tx * 8];
            ulonglong2 b1 = *(const ulonglong2*)&Ks[buf][kk][tx * 8 + 4];
            unsigned long long bp[4] = {b0.x, b0.y, b1.x, b1.y};
            float ra[8] = {a0.x, a0.y, a0.z, a0.w, a1.x, a1.y, a1.z, a1.w};
            #pragma unroll
            for (int i = 0; i < 8; i++) {
                unsigned long long ap; SPLAT2(ap, ra[i]);
                #pragma unroll
                for (int j = 0; j < 4; j++) FMA2(acc[i][j], ap, bp[j]);
            }
        }
        if (t + 1 < T) {
            int nbuf = buf ^ 1;
            Qs[nbuf][ac4 + 0][ar] = nq.x; Qs[nbuf][ac4 + 1][ar] = nq.y;
            Qs[nbuf][ac4 + 2][ar] = nq.z; Qs[nbuf][ac4 + 3][ar] = nq.w;
            Ks[nbuf][ac4 + 0][ar] = nk.x; Ks[nbuf][ac4 + 1][ar] = nk.y;
            Ks[nbuf][ac4 + 2][ar] = nk.z; Ks[nbuf][ac4 + 3][ar] = nk.w;
        }
        __syncthreads();
    }

    const float scale = 0.125f;  // 1/sqrt(64)
    #pragma unroll
    for (int i = 0; i < 8; i++) {
        int qr = row0 + ty * 8 + i;
        float* orow = Wout + ((size_t)bh * Sn + qr) * Sn;
        #pragma unroll
        for (int j = 0; j < 4; j++) {
            unsigned lo, hi; UNPK2(lo, hi, acc[i][j]);
            int kc = col0 + tx * 8 + 2 * j;
            orow[kc]     = __uint_as_float(lo) * scale + mask[b * Sn + kc];
            orow[kc + 1] = __uint_as_float(hi) * scale + mask[b * Sn + kc + 1];
        }
    }
}

// ---------------------------------------------------------------------------
// Kernel 3: row softmax (unchanged from R1 — memory bound, passed correctness).
// ---------------------------------------------------------------------------
__global__ __launch_bounds__(256) void softmax_kernel(float* __restrict__ Wm) {
    __shared__ float buf[Sn];
    __shared__ float red[8];
    int row = blockIdx.x;
    int q = row & (Sn - 1);
    int len = q + 1;
    float* wrow = Wm + (size_t)row * Sn;
    int tid = threadIdx.x;
    int lane = tid & 31, warp = tid >> 5;

    float mx = -1e30f;
    for (int c = tid; c < len; c += 256) {
        float v = wrow[c];
        buf[c] = v;
        mx = fmaxf(mx, v);
    }
    #pragma unroll
    for (int o = 16; o > 0; o >>= 1) mx = fmaxf(mx, __shfl_xor_sync(0xffffffffu, mx, o));
    if (lane == 0) red[warp] = mx;
    __syncthreads();
    if (tid < 32) {
        float t = (tid < 8) ? red[tid] : -1e30f;
        #pragma unroll
        for (int o = 4; o > 0; o >>= 1) t = fmaxf(t, __shfl_xor_sync(0xffffffffu, t, o));
        if (tid == 0) red[0] = t;
    }
    __syncthreads();
    mx = red[0];
    __syncthreads();

    float sum = 0.0f;
    for (int c = tid; c < len; c += 256) {
        float e = __expf(buf[c] - mx);
        buf[c] = e;
        sum += e;
    }
    #pragma unroll
    for (int o = 16; o > 0; o >>= 1) sum += __shfl_xor_sync(0xffffffffu, sum, o);
    if (lane == 0) red[warp] = sum;
    __syncthreads();
    if (tid < 32) {
        float t = (tid < 8) ? red[tid] : 0.0f;
        #pragma unroll
        for (int o = 4; o > 0; o >>= 1) t += __shfl_xor_sync(0xffffffffu, t, o);
        if (tid == 0) red[0] = t;
    }
    __syncthreads();
    float inv = 1.0f / red[0];

    for (int c = tid; c < Sn; c += 256) {
        wrow[c] = (c < len) ? buf[c] * inv : 0.0f;
    }
}

// ---------------------------------------------------------------------------
// Kernel 4: attn_heads = weights @ v per (b,h). 128q x 64d tile, kt=16, DB,
// FFMA2 with row-paired accumulators (a from smem as packed pairs, b splat).
// Iterates only k-blocks <= q-block (upper-tri weights are exact zeros).
// ---------------------------------------------------------------------------
__global__ __launch_bounds__(256) void av_kernel(const float* __restrict__ Wm) {
    int qb = blockIdx.x, bh = blockIdx.y;
    const float* wrow = Wm + (size_t)bh * Sn * Sn;
    const float* vp = g_v + (size_t)bh * Sn * HDn;
    __shared__ __align__(16) float Ws[2][16][132];
    __shared__ __align__(16) float Vs[2][16][68];
    int tid = threadIdx.x;
    int tx = tid & 15, ty = tid >> 4;
    int row0 = qb * 128;
    int wr = tid >> 1, wc8 = (tid & 1) * 8;
    int vr = tid >> 4, vc4 = (tid & 15) * 4;
    const float* Wptr = wrow + (size_t)(row0 + wr) * Sn + wc8;
    const float* Vptr = vp + (size_t)vr * HDn + vc4;

    {
        float4 w0 = *(const float4*)Wptr;
        float4 w1 = *(const float4*)(Wptr + 4);
        Ws[0][wc8 + 0][wr] = w0.x; Ws[0][wc8 + 1][wr] = w0.y;
        Ws[0][wc8 + 2][wr] = w0.z; Ws[0][wc8 + 3][wr] = w0.w;
        Ws[0][wc8 + 4][wr] = w1.x; Ws[0][wc8 + 5][wr] = w1.y;
        Ws[0][wc8 + 6][wr] = w1.z; Ws[0][wc8 + 7][wr] = w1.w;
        *(float4*)&Vs[0][vr][vc4] = *(const float4*)Vptr;
    }
    __syncthreads();

    unsigned long long acc[4][4];   // 4 row-pairs x 4 cols
    #pragma unroll
    for (int i = 0; i < 4; i++)
        #pragma unroll
        for (int j = 0; j < 4; j++) acc[i][j] = 0ull;

    const int T = (qb + 1) * 8;     // kend / 16
    for (int t = 0; t < T; t++) {
        int buf = t & 1;
        float4 nw0, nw1, nv;
        if (t + 1 < T) {
            nw0 = *(const float4*)(Wptr + (t + 1) * 16);
            nw1 = *(const float4*)(Wptr + (t + 1) * 16 + 4);
            nv  = *(const float4*)(Vptr + (size_t)(t + 1) * 16 * HDn);
        }
        #pragma unroll
        for (int kk = 0; kk < 16; kk++) {
            ulonglong2 ap0 = *(const ulonglong2*)&Ws[buf][kk][ty * 8];
            ulonglong2 ap1 = *(const ulonglong2*)&Ws[buf][kk][ty * 8 + 4];
            unsigned long long ap[4] = {ap0.x, ap0.y, ap1.x, ap1.y};
            float4 bv = *(const float4*)&Vs[buf][kk][tx * 4];
            float rb[4] = {bv.x, bv.y, bv.z, bv.w};
            #pragma unroll
            for (int j = 0; j < 4; j++) {
                unsigned long long bp; SPLAT2(bp, rb[j]);
                #pragma unroll
                for (int i = 0; i < 4; i++) FMA2(acc[i][j], ap[i], bp);
            }
        }
        if (t + 1 < T) {
            int nbuf = buf ^ 1;
            Ws[nbuf][wc8 + 0][wr] = nw0.x; Ws[nbuf][wc8 + 1][wr] = nw0.y;
            Ws[nbuf][wc8 + 2][wr] = nw0.z; Ws[nbuf][wc8 + 3][wr] = nw0.w;
            Ws[nbuf][wc8 + 4][wr] = nw1.x; Ws[nbuf][wc8 + 5][wr] = nw1.y;
            Ws[nbuf][wc8 + 6][wr] = nw1.z; Ws[nbuf][wc8 + 7][wr] = nw1.w;
            *(float4*)&Vs[nbuf][vr][vc4] = nv;
        }
        __syncthreads();
    }

    #pragma unroll
    for (int i = 0; i < 4; i++) {
        #pragma unroll
        for (int j = 0; j < 4; j++) {
            unsigned lo, hi; UNPK2(lo, hi, acc[i][j]);
            int r0 = row0 + ty * 8 + 2 * i;
            int c = tx * 4 + j;
            g_att[((size_t)bh * Sn + r0) * HDn + c]     = __uint_as_float(lo);
            g_att[((size_t)bh * Sn + r0 + 1) * HDn + c] = __uint_as_float(hi);
        }
    }
}

// ---------------------------------------------------------------------------
// Kernel 5: output projection with head-transpose folded into A loads.
// out[4096,1024] = A @ w_proj + b_proj. Same DB/FFMA2 scheme as qkv.
// ---------------------------------------------------------------------------
__global__ __launch_bounds__(256) void proj_gemm(const float* __restrict__ W,
                                                 const float* __restrict__ bias,
                                                 float* __restrict__ out) {
    const int K = 1024, N = 1024;
    __shared__ __align__(16) float As[2][8][132];
    __shared__ __align__(16) float Bs[2][8][132];
    int tid = threadIdx.x;
    int tx = tid & 15, ty = tid >> 4;
    int row0 = blockIdx.y * 128, col0 = blockIdx.x * 128;
    int ar = tid >> 1, ac4 = (tid & 1) * 4;
    int br = tid >> 5, bc4 = (tid & 31) * 4;
    int arow = row0 + ar;
    int ab = arow >> 11, as = arow & 2047;
    // A[arow, c] = g_att[((ab*H + c>>6)*S + as)*64 + (c&63)]
    size_t abase = ((size_t)ab * Hn * Sn + as) * HDn;
    const float* Bptr = W + (size_t)br * N + col0 + bc4;

    {
        int c = ac4;
        float4 av = *(const float4*)&g_att[abase + (size_t)(c >> 6) * Sn * HDn + (c & 63)];
        float4 bv = *(const float4*)Bptr;
        As[0][ac4 + 0][ar] = av.x; As[0][ac4 + 1][ar] = av.y;
        As[0][ac4 + 2][ar] = av.z; As[0][ac4 + 3][ar] = av.w;
        *(float4*)&Bs[0][br][bc4] = bv;
    }
    __syncthreads();

    unsigned long long acc[8][4];
    #pragma unroll
    for (int i = 0; i < 8; i++)
        #pragma unroll
        for (int j = 0; j < 4; j++) acc[i][j] = 0ull;

    const int T = K / 8;
    for (int t = 0; t < T; t++) {
        int buf = t & 1;
        float4 na, nb;
        if (t + 1 < T) {
            int c = (t + 1) * 8 + ac4;
            na = *(const float4*)&g_att[abase + (size_t)(c >> 6) * Sn * HDn + (c & 63)];
            nb = *(const float4*)(Bptr + (size_t)(t + 1) * 8 * N);
        }
        #pragma unroll
        for (int kk = 0; kk < 8; kk++) {
            float4 a0 = *(const float4*)&As[buf][kk][ty * 8];
            float4 a1 = *(const float4*)&As[buf][kk][ty * 8 + 4];
            ulonglong2 b0 = *(const ulonglong2*)&Bs[buf][kk][tx * 8];
            ulonglong2 b1 = *(const ulonglong2*)&Bs[buf][kk][tx * 8 + 4];
            unsigned long long bp[4] = {b0.x, b0.y, b1.x, b1.y};
            float ra[8] = {a0.x, a0.y, a0.z, a0.w, a1.x, a1.y, a1.z, a1.w};
            #pragma unroll
            for (int i = 0; i < 8; i++) {
                unsigned long long ap; SPLAT2(ap, ra[i]);
                #pragma unroll
                for (int j = 0; j < 4; j++) FMA2(acc[i][j], ap, bp[j]);
            }
        }
        if (t + 1 < T) {
            int nbuf = buf ^ 1;
            As[nbuf][ac4 + 0][ar] = na.x; As[nbuf][ac4 + 1][ar] = na.y;
            As[nbuf][ac4 + 2][ar] = na.z; As[nbuf][ac4 + 3][ar] = na.w;
            *(float4*)&Bs[nbuf][br][bc4] = nb;
        }
        __syncthreads();
    }

    #pragma unroll
    for (int i = 0; i < 8; i++) {
        int r = row0 + ty * 8 + i;
        #pragma unroll
        for (int j = 0; j < 4; j++) {
            unsigned lo, hi; UNPK2(lo, hi, acc[i][j]);
            int c = col0 + tx * 8 + 2 * j;
            out[(size_t)r * N + c]     = __uint_as_float(lo) + bias[c];
            out[(size_t)r * N + c + 1] = __uint_as_float(hi) + bias[c + 1];
        }
    }
}

// ---------------------------------------------------------------------------
extern "C" void kernel_launch(void* const* d_in, const int* in_sizes, int n_in,
                              void* d_out, int out_size) {
    (void)in_sizes; (void)n_in; (void)out_size;
    const float* hs     = (const float*)d_in[0];
    const float* mask   = (const float*)d_in[1];
    const float* w_attn = (const float*)d_in[2];
    const float* b_attn = (const float*)d_in[3];
    const float* w_proj = (const float*)d_in[4];
    const float* b_proj = (const float*)d_in[5];

    float* attn_out = (float*)d_out;                          // [B,S,D]
    float* weights  = (float*)d_out + (size_t)Bn * Sn * Dn;   // [B,H,S,S]

    qkv_gemm<<<dim3(N3D / 128, BSn / 128), 256>>>(hs, w_attn, b_attn);
    scores_kernel<<<dim3(136, Bn * Hn), 256>>>(mask, weights);
    softmax_kernel<<<dim3(Bn * Hn * Sn), 256>>>(weights);
    av_kernel<<<dim3(Sn / 128, Bn * Hn), 256>>>(weights);
    proj_gemm<<<dim3(Dn / 128, BSn / 128), 256>>>(w_proj, b_proj, attn_out);
}

// round 3
// speedup vs baseline: 1.6867x; 1.4184x over previous
#include <cuda_runtime.h>
#include <cuda_bf16.h>
#include <math.h>
#include <stdint.h>

#define Bn 2
#define Sn 2048
#define Dn 1024
#define Hn 16
#define HDn 64
#define BSn (Bn*Sn)      // 4096
#define N3D (3*Dn)       // 3072

// Scratch (device globals — no allocation in kernel_launch)
__device__ float g_q[Bn*Hn*Sn*HDn];
__device__ float g_k[Bn*Hn*Sn*HDn];
__device__ float g_v[Bn*Hn*Sn*HDn];
__device__ float g_att[Bn*Hn*Sn*HDn];

// ---------------------------------------------------------------------------
// helpers
// ---------------------------------------------------------------------------
__device__ __forceinline__ uint32_t s2u(const void* p) {
    return (uint32_t)__cvta_generic_to_shared(p);
}
__device__ __forceinline__ void ldsm4(uint32_t& r0, uint32_t& r1, uint32_t& r2,
                                      uint32_t& r3, uint32_t a) {
    asm volatile("ldmatrix.sync.aligned.m8n8.x4.shared.b16 {%0,%1,%2,%3},[%4];"
                 : "=r"(r0), "=r"(r1), "=r"(r2), "=r"(r3) : "r"(a));
}
#define MMA(c, a, b) asm volatile( \
    "mma.sync.aligned.m16n8k16.row.col.f32.bf16.bf16.f32 " \
    "{%0,%1,%2,%3},{%4,%5,%6,%7},{%8,%9},{%0,%1,%2,%3};" \
    : "+f"((c)[0]), "+f"((c)[1]), "+f"((c)[2]), "+f"((c)[3]) \
    : "r"((a)[0]), "r"((a)[1]), "r"((a)[2]), "r"((a)[3]), "r"((b)[0]), "r"((b)[1]))

// split pair (x,y) into packed bf16x2 hi and lo words (mem order: x=low half)
__device__ __forceinline__ void split2(float x, float y, uint32_t& ph, uint32_t& pl) {
    uint32_t h;
    asm("cvt.rn.bf16x2.f32 %0, %1, %2;" : "=r"(h) : "f"(y), "f"(x));
    float hx = __uint_as_float(h << 16);
    float hy = __uint_as_float(h & 0xffff0000u);
    ph = h;
    float lx = x - hx, ly = y - hy;
    asm("cvt.rn.bf16x2.f32 %0, %1, %2;" : "=r"(pl) : "f"(ly), "f"(lx));
}
__device__ __forceinline__ void split1(float x, __nv_bfloat16& h, __nv_bfloat16& l) {
    h = __float2bfloat16(x);
    l = __float2bfloat16(x - __bfloat162float(h));
}

// Shared tile shapes (uniform across mma kernels):
//   A: [2][128][24] bf16 hi+lo   (m-major rows, k contiguous, 24 = 16 + 8 pad)
//   B: [2][64][24]  bf16 hi+lo   (n-major rows, k contiguous)
// warp layout: 8 warps, warp tile 32m x 32n; m-frags 2, n-frags 4.

// ---------------------------------------------------------------------------
// Kernel 1: QKV projection. [4096,1024] @ [1024,3072] + b -> q/k/v per-head
// block tile 128x64, k16 stages, double buffered, 3-term bf16-split MMA.
// ---------------------------------------------------------------------------
__global__ __launch_bounds__(256, 2) void qkv_gemm(const float* __restrict__ A,
                                                   const float* __restrict__ W,
                                                   const float* __restrict__ bias) {
    const int K = 1024, N = N3D;
    __shared__ __nv_bfloat16 Ah[2][128][24], Al[2][128][24];
    __shared__ __nv_bfloat16 Bh[2][64][24],  Bl[2][64][24];
    int tid = threadIdx.x, lane = tid & 31, wid = tid >> 5;
    int row0 = blockIdx.y * 128, col0 = blockIdx.x * 64;
    int mbase = (wid & 3) * 32, nbase = (wid >> 2) * 32;
    // staging indices
    int sar = tid >> 1, sah = (tid & 1) * 8;            // A: 128 rows x 16
    int sbk = tid >> 4, sbc = (tid & 15) * 4;           // B: 16 k-rows x 64 n
    const float* Aptr = A + (size_t)(row0 + sar) * K + sah;
    const float* Bptr = W + (size_t)sbk * N + col0 + sbc;
    // fragment lane offsets
    int a_row = lane & 15;
    int a_colb = (lane >> 4) * 16;
    int b_row = (lane & 7) + ((lane >> 4) << 3);
    int b_colb = (lane & 8) ? 16 : 0;

    float acc[2][4][4] = {};

    // prologue stage 0
    {
        float4 u = *(const float4*)Aptr;
        float4 v = *(const float4*)(Aptr + 4);
        uint32_t ph[4], pl[4];
        split2(u.x, u.y, ph[0], pl[0]); split2(u.z, u.w, ph[1], pl[1]);
        split2(v.x, v.y, ph[2], pl[2]); split2(v.z, v.w, ph[3], pl[3]);
        *(uint4*)&Ah[0][sar][sah] = make_uint4(ph[0], ph[1], ph[2], ph[3]);
        *(uint4*)&Al[0][sar][sah] = make_uint4(pl[0], pl[1], pl[2], pl[3]);
        float4 w = *(const float4*)Bptr;
        float wf[4] = {w.x, w.y, w.z, w.w};
        #pragma unroll
        for (int j = 0; j < 4; j++) {
            __nv_bfloat16 h, l; split1(wf[j], h, l);
            Bh[0][sbc + j][sbk] = h; Bl[0][sbc + j][sbk] = l;
        }
    }
    __syncthreads();

    const int T = K / 16;
    for (int t = 0; t < T; t++) {
        int buf = t & 1;
        float4 na0, na1, nb;
        if (t + 1 < T) {
            na0 = *(const float4*)(Aptr + (t + 1) * 16);
            na1 = *(const float4*)(Aptr + (t + 1) * 16 + 4);
            nb  = *(const float4*)(Bptr + (size_t)(t + 1) * 16 * N);
        }
        // fragments
        uint32_t ahf[2][4], alf[2][4], bhf[4][2], blf[4][2];
        #pragma unroll
        for (int i = 0; i < 2; i++) {
            uint32_t a0 = s2u(&Ah[buf][mbase + i * 16 + a_row][0]) + a_colb;
            ldsm4(ahf[i][0], ahf[i][1], ahf[i][2], ahf[i][3], a0);
            uint32_t a1 = s2u(&Al[buf][mbase + i * 16 + a_row][0]) + a_colb;
            ldsm4(alf[i][0], alf[i][1], alf[i][2], alf[i][3], a1);
        }
        #pragma unroll
        for (int jg = 0; jg < 2; jg++) {
            uint32_t r0, r1, r2, r3;
            uint32_t ba = s2u(&Bh[buf][nbase + jg * 16 + b_row][0]) + b_colb;
            ldsm4(r0, r1, r2, r3, ba);
            bhf[jg * 2][0] = r0; bhf[jg * 2][1] = r1;
            bhf[jg * 2 + 1][0] = r2; bhf[jg * 2 + 1][1] = r3;
            uint32_t bb = s2u(&Bl[buf][nbase + jg * 16 + b_row][0]) + b_colb;
            ldsm4(r0, r1, r2, r3, bb);
            blf[jg * 2][0] = r0; blf[jg * 2][1] = r1;
            blf[jg * 2 + 1][0] = r2; blf[jg * 2 + 1][1] = r3;
        }
        #pragma unroll
        for (int i = 0; i < 2; i++)
            #pragma unroll
            for (int j = 0; j < 4; j++) {
                MMA(acc[i][j], ahf[i], bhf[j]);
                MMA(acc[i][j], ahf[i], blf[j]);
                MMA(acc[i][j], alf[i], bhf[j]);
            }
        if (t + 1 < T) {
            int nbuf = buf ^ 1;
            uint32_t ph[4], pl[4];
            split2(na0.x, na0.y, ph[0], pl[0]); split2(na0.z, na0.w, ph[1], pl[1]);
            split2(na1.x, na1.y, ph[2], pl[2]); split2(na1.z, na1.w, ph[3], pl[3]);
            *(uint4*)&Ah[nbuf][sar][sah] = make_uint4(ph[0], ph[1], ph[2], ph[3]);
            *(uint4*)&Al[nbuf][sar][sah] = make_uint4(pl[0], pl[1], pl[2], pl[3]);
            float wf[4] = {nb.x, nb.y, nb.z, nb.w};
            #pragma unroll
            for (int j = 0; j < 4; j++) {
                __nv_bfloat16 h, l; split1(wf[j], h, l);
                Bh[nbuf][sbc + j][sbk] = h; Bl[nbuf][sbc + j][sbk] = l;
            }
        }
        __syncthreads();
    }

    // epilogue: scatter into g_q/g_k/g_v
    #pragma unroll
    for (int i = 0; i < 2; i++) {
        #pragma unroll
        for (int j = 0; j < 4; j++) {
            int rr = row0 + mbase + i * 16 + (lane >> 2);
            int cc = col0 + nbase + j * 8 + (lane & 3) * 2;
            #pragma unroll
            for (int half = 0; half < 2; half++) {
                int r = rr + half * 8;
                float v0 = acc[i][j][half * 2 + 0];
                float v1 = acc[i][j][half * 2 + 1];
                int b = r >> 11, s = r & 2047;
                #pragma unroll
                for (int e = 0; e < 2; e++) {
                    int c = cc + e;
                    float v = (e ? v1 : v0) + bias[c];
                    int which = c >> 10;
                    int dcol = c & 1023;
                    int h = dcol >> 6, hd = dcol & 63;
                    float* dst = (which == 0) ? g_q : (which == 1) ? g_k : g_v;
                    dst[(size_t)(((b * Hn) + h) * Sn + s) * HDn + hd] = v;
                }
            }
        }
    }
}

// ---------------------------------------------------------------------------
// Kernel 2: attention scores, lower-tri blocks (128q x 64k tiles), K=64.
// B (K-matrix) is already k-major: direct staging, no transpose.
// ---------------------------------------------------------------------------
__global__ __launch_bounds__(256, 2) void scores_kernel(const float* __restrict__ mask,
                                                        float* __restrict__ Wout) {
    int idx = blockIdx.x;    // 0..271: cum(qb) = qb^2+qb
    int qb = (int)((sqrtf(4.0f * idx + 1.0f) - 1.0f) * 0.5f);
    while ((qb + 1) * (qb + 2) <= idx) qb++;
    while (qb * (qb + 1) > idx) qb--;
    int kb = idx - qb * (qb + 1);
    int bh = blockIdx.y;
    int bb = bh >> 4;
    const float* qp = g_q + (size_t)bh * Sn * HDn;
    const float* kp = g_k + (size_t)bh * Sn * HDn;

    __shared__ __nv_bfloat16 Ah[2][128][24], Al[2][128][24];
    __shared__ __nv_bfloat16 Bh[2][64][24],  Bl[2][64][24];
    int tid = threadIdx.x, lane = tid & 31, wid = tid >> 5;
    int row0 = qb * 128, col0 = kb * 64;
    int mbase = (wid & 3) * 32, nbase = (wid >> 2) * 32;
    int sar = tid >> 1, sah = (tid & 1) * 8;
    int sbr = tid >> 2, sbh = (tid & 3) * 4;        // B: 64 rows x 16, 4 floats each
    const float* Aptr = qp + (size_t)(row0 + sar) * HDn + sah;
    const float* Bptr = kp + (size_t)(col0 + sbr) * HDn + sbh;
    int a_row = lane & 15;
    int a_colb = (lane >> 4) * 16;
    int b_row = (lane & 7) + ((lane >> 4) << 3);
    int b_colb = (lane & 8) ? 16 : 0;

    float acc[2][4][4] = {};

    {
        float4 u = *(const float4*)Aptr;
        float4 v = *(const float4*)(Aptr + 4);
        uint32_t ph[4], pl[4];
        split2(u.x, u.y, ph[0], pl[0]); split2(u.z, u.w, ph[1], pl[1]);
        split2(v.x, v.y, ph[2], pl[2]); split2(v.z, v.w, ph[3], pl[3]);
        *(uint4*)&Ah[0][sar][sah] = make_uint4(ph[0], ph[1], ph[2], ph[3]);
        *(uint4*)&Al[0][sar][sah] = make_uint4(pl[0], pl[1], pl[2], pl[3]);
        float4 w = *(const float4*)Bptr;
        uint32_t qh[2], ql[2];
        split2(w.x, w.y, qh[0], ql[0]); split2(w.z, w.w, qh[1], ql[1]);
        *(uint2*)&Bh[0][sbr][sbh] = make_uint2(qh[0], qh[1]);
        *(uint2*)&Bl[0][sbr][sbh] = make_uint2(ql[0], ql[1]);
    }
    __syncthreads();

    const int T = HDn / 16;   // 4
    for (int t = 0; t < T; t++) {
        int buf = t & 1;
        float4 na0, na1, nb;
        if (t + 1 < T) {
            na0 = *(const float4*)(Aptr + (t + 1) * 16);
            na1 = *(const float4*)(Aptr + (t + 1) * 16 + 4);
            nb  = *(const float4*)(Bptr + (t + 1) * 16);
        }
        uint32_t ahf[2][4], alf[2][4], bhf[4][2], blf[4][2];
        #pragma unroll
        for (int i = 0; i < 2; i++) {
            uint32_t a0 = s2u(&Ah[buf][mbase + i * 16 + a_row][0]) + a_colb;
            ldsm4(ahf[i][0], ahf[i][1], ahf[i][2], ahf[i][3], a0);
            uint32_t a1 = s2u(&Al[buf][mbase + i * 16 + a_row][0]) + a_colb;
            ldsm4(alf[i][0], alf[i][1], alf[i][2], alf[i][3], a1);
        }
        #pragma unroll
        for (int jg = 0; jg < 2; jg++) {
            uint32_t r0, r1, r2, r3;
            uint32_t ba = s2u(&Bh[buf][nbase + jg * 16 + b_row][0]) + b_colb;
            ldsm4(r0, r1, r2, r3, ba);
            bhf[jg * 2][0] = r0; bhf[jg * 2][1] = r1;
            bhf[jg * 2 + 1][0] = r2; bhf[jg * 2 + 1][1] = r3;
            uint32_t bb = s2u(&Bl[buf][nbase + jg * 16 + b_row][0]) + b_colb;
            ldsm4(r0, r1, r2, r3, bb);
            blf[jg * 2][0] = r0; blf[jg * 2][1] = r1;
            blf[jg * 2 + 1][0] = r2; blf[jg * 2 + 1][1] = r3;
        }
        #pragma unroll
        for (int i = 0; i < 2; i++)
            #pragma unroll
            for (int j = 0; j < 4; j++) {
                MMA(acc[i][j], ahf[i], bhf[j]);
                MMA(acc[i][j], ahf[i], blf[j]);
                MMA(acc[i][j], alf[i], bhf[j]);
            }
        if (t + 1 < T) {
            int nbuf = buf ^ 1;
            uint32_t ph[4], pl[4];
            split2(na0.x, na0.y, ph[0], pl[0]); split2(na0.z, na0.w, ph[1], pl[1]);
            split2(na1.x, na1.y, ph[2], pl[2]); split2(na1.z, na1.w, ph[3], pl[3]);
            *(uint4*)&Ah[nbuf][sar][sah] = make_uint4(ph[0], ph[1], ph[2], ph[3]);
            *(uint4*)&Al[nbuf][sar][sah] = make_uint4(pl[0], pl[1], pl[2], pl[3]);
            uint32_t qh[2], ql[2];
            split2(nb.x, nb.y, qh[0], ql[0]); split2(nb.z, nb.w, qh[1], ql[1]);
            *(uint2*)&Bh[nbuf][sbr][sbh] = make_uint2(qh[0], qh[1]);
            *(uint2*)&Bl[nbuf][sbr][sbh] = make_uint2(ql[0], ql[1]);
        }
        __syncthreads();
    }

    const float scale = 0.125f;
    #pragma unroll
    for (int i = 0; i < 2; i++) {
        #pragma unroll
        for (int j = 0; j < 4; j++) {
            int rr = row0 + mbase + i * 16 + (lane >> 2);
            int cc = col0 + nbase + j * 8 + (lane & 3) * 2;
            #pragma unroll
            for (int half = 0; half < 2; half++) {
                int r = rr + half * 8;
                float* orow = Wout + ((size_t)bh * Sn + r) * Sn;
                orow[cc]     = acc[i][j][half * 2 + 0] * scale + mask[bb * Sn + cc];
                orow[cc + 1] = acc[i][j][half * 2 + 1] * scale + mask[bb * Sn + cc + 1];
            }
        }
    }
}

// ---------------------------------------------------------------------------
// Kernel 3: row softmax (unchanged — memory bound).
// ---------------------------------------------------------------------------
__global__ __launch_bounds__(256) void softmax_kernel(float* __restrict__ Wm) {
    __shared__ float buf[Sn];
    __shared__ float red[8];
    int row = blockIdx.x;
    int q = row & (Sn - 1);
    int len = q + 1;
    float* wrow = Wm + (size_t)row * Sn;
    int tid = threadIdx.x;
    int lane = tid & 31, warp = tid >> 5;

    float mx = -1e30f;
    for (int c = tid; c < len; c += 256) {
        float v = wrow[c];
        buf[c] = v;
        mx = fmaxf(mx, v);
    }
    #pragma unroll
    for (int o = 16; o > 0; o >>= 1) mx = fmaxf(mx, __shfl_xor_sync(0xffffffffu, mx, o));
    if (lane == 0) red[warp] = mx;
    __syncthreads();
    if (tid < 32) {
        float t = (tid < 8) ? red[tid] : -1e30f;
        #pragma unroll
        for (int o = 4; o > 0; o >>= 1) t = fmaxf(t, __shfl_xor_sync(0xffffffffu, t, o));
        if (tid == 0) red[0] = t;
    }
    __syncthreads();
    mx = red[0];
    __syncthreads();

    float sum = 0.0f;
    for (int c = tid; c < len; c += 256) {
        float e = __expf(buf[c] - mx);
        buf[c] = e;
        sum += e;
    }
    #pragma unroll
    for (int o = 16; o > 0; o >>= 1) sum += __shfl_xor_sync(0xffffffffu, sum, o);
    if (lane == 0) red[warp] = sum;
    __syncthreads();
    if (tid < 32) {
        float t = (tid < 8) ? red[tid] : 0.0f;
        #pragma unroll
        for (int o = 4; o > 0; o >>= 1) t += __shfl_xor_sync(0xffffffffu, t, o);
        if (tid == 0) red[0] = t;
    }
    __syncthreads();
    float inv = 1.0f / red[0];

    for (int c = tid; c < Sn; c += 256) {
        wrow[c] = (c < len) ? buf[c] * inv : 0.0f;
    }
}

// ---------------------------------------------------------------------------
// Kernel 4: attn_heads = weights @ V per (b,h). 128q x 64d tile; k-loop over
// causal prefix only. V staged transposed ([hd][k]).
// ---------------------------------------------------------------------------
__global__ __launch_bounds__(256, 2) void av_kernel(const float* __restrict__ Wm) {
    int qb = gridDim.x - 1 - blockIdx.x;   // longest blocks first
    int bh = blockIdx.y;
    const float* wrow = Wm + (size_t)bh * Sn * Sn;
    const float* vp = g_v + (size_t)bh * Sn * HDn;

    __shared__ __nv_bfloat16 Ah[2][128][24], Al[2][128][24];
    __shared__ __nv_bfloat16 Bh[2][64][24],  Bl[2][64][24];
    int tid = threadIdx.x, lane = tid & 31, wid = tid >> 5;
    int row0 = qb * 128;
    int mbase = (wid & 3) * 32, nbase = (wid >> 2) * 32;
    int sar = tid >> 1, sah = (tid & 1) * 8;
    int sbk = tid >> 4, sbc = (tid & 15) * 4;   // 16 k-rows x 64 hd
    const float* Aptr = wrow + (size_t)(row0 + sar) * Sn + sah;
    const float* Bptr = vp + (size_t)sbk * HDn + sbc;
    int a_row = lane & 15;
    int a_colb = (lane >> 4) * 16;
    int b_row = (lane & 7) + ((lane >> 4) << 3);
    int b_colb = (lane & 8) ? 16 : 0;

    float acc[2][4][4] = {};

    {
        float4 u = *(const float4*)Aptr;
        float4 v = *(const float4*)(Aptr + 4);
        uint32_t ph[4], pl[4];
        split2(u.x, u.y, ph[0], pl[0]); split2(u.z, u.w, ph[1], pl[1]);
        split2(v.x, v.y, ph[2], pl[2]); split2(v.z, v.w, ph[3], pl[3]);
        *(uint4*)&Ah[0][sar][sah] = make_uint4(ph[0], ph[1], ph[2], ph[3]);
        *(uint4*)&Al[0][sar][sah] = make_uint4(pl[0], pl[1], pl[2], pl[3]);
        float4 w = *(const float4*)Bptr;
        float wf[4] = {w.x, w.y, w.z, w.w};
        #pragma unroll
        for (int j = 0; j < 4; j++) {
            __nv_bfloat16 h, l; split1(wf[j], h, l);
            Bh[0][sbc + j][sbk] = h; Bl[0][sbc + j][sbk] = l;
        }
    }
    __syncthreads();

    const int T = (qb + 1) * 8;   // causal prefix in k16 steps
    for (int t = 0; t < T; t++) {
        int buf = t & 1;
        float4 na0, na1, nb;
        if (t + 1 < T) {
            na0 = *(const float4*)(Aptr + (t + 1) * 16);
            na1 = *(const float4*)(Aptr + (t + 1) * 16 + 4);
            nb  = *(const float4*)(Bptr + (size_t)(t + 1) * 16 * HDn);
        }
        uint32_t ahf[2][4], alf[2][4], bhf[4][2], blf[4][2];
        #pragma unroll
        for (int i = 0; i < 2; i++) {
            uint32_t a0 = s2u(&Ah[buf][mbase + i * 16 + a_row][0]) + a_colb;
            ldsm4(ahf[i][0], ahf[i][1], ahf[i][2], ahf[i][3], a0);
            uint32_t a1 = s2u(&Al[buf][mbase + i * 16 + a_row][0]) + a_colb;
            ldsm4(alf[i][0], alf[i][1], alf[i][2], alf[i][3], a1);
        }
        #pragma unroll
        for (int jg = 0; jg < 2; jg++) {
            uint32_t r0, r1, r2, r3;
            uint32_t ba = s2u(&Bh[buf][nbase + jg * 16 + b_row][0]) + b_colb;
            ldsm4(r0, r1, r2, r3, ba);
            bhf[jg * 2][0] = r0; bhf[jg * 2][1] = r1;
            bhf[jg * 2 + 1][0] = r2; bhf[jg * 2 + 1][1] = r3;
            uint32_t bb = s2u(&Bl[buf][nbase + jg * 16 + b_row][0]) + b_colb;
            ldsm4(r0, r1, r2, r3, bb);
            blf[jg * 2][0] = r0; blf[jg * 2][1] = r1;
            blf[jg * 2 + 1][0] = r2; blf[jg * 2 + 1][1] = r3;
        }
        #pragma unroll
        for (int i = 0; i < 2; i++)
            #pragma unroll
            for (int j = 0; j < 4; j++) {
                MMA(acc[i][j], ahf[i], bhf[j]);
                MMA(acc[i][j], ahf[i], blf[j]);
                MMA(acc[i][j], alf[i], bhf[j]);
            }
        if (t + 1 < T) {
            int nbuf = buf ^ 1;
            uint32_t ph[4], pl[4];
            split2(na0.x, na0.y, ph[0], pl[0]); split2(na0.z, na0.w, ph[1], pl[1]);
            split2(na1.x, na1.y, ph[2], pl[2]); split2(na1.z, na1.w, ph[3], pl[3]);
            *(uint4*)&Ah[nbuf][sar][sah] = make_uint4(ph[0], ph[1], ph[2], ph[3]);
            *(uint4*)&Al[nbuf][sar][sah] = make_uint4(pl[0], pl[1], pl[2], pl[3]);
            float wf[4] = {nb.x, nb.y, nb.z, nb.w};
            #pragma unroll
            for (int j = 0; j < 4; j++) {
                __nv_bfloat16 h, l; split1(wf[j], h, l);
                Bh[nbuf][sbc + j][sbk] = h; Bl[nbuf][sbc + j][sbk] = l;
            }
        }
        __syncthreads();
    }

    #pragma unroll
    for (int i = 0; i < 2; i++) {
        #pragma unroll
        for (int j = 0; j < 4; j++) {
            int rr = row0 + mbase + i * 16 + (lane >> 2);
            int cc = nbase + j * 8 + (lane & 3) * 2;
            #pragma unroll
            for (int half = 0; half < 2; half++) {
                int r = rr + half * 8;
                float* orow = g_att + ((size_t)bh * Sn + r) * HDn;
                orow[cc]     = acc[i][j][half * 2 + 0];
                orow[cc + 1] = acc[i][j][half * 2 + 1];
            }
        }
    }
}

// ---------------------------------------------------------------------------
// Kernel 5: output projection, head-transpose folded into A staging.
// ---------------------------------------------------------------------------
__global__ __launch_bounds__(256, 2) void proj_gemm(const float* __restrict__ W,
                                                    const float* __restrict__ bias,
                                                    float* __restrict__ out) {
    const int K = 1024, N = 1024;
    __shared__ __nv_bfloat16 Ah[2][128][24], Al[2][128][24];
    __shared__ __nv_bfloat16 Bh[2][64][24],  Bl[2][64][24];
    int tid = threadIdx.x, lane = tid & 31, wid = tid >> 5;
    int row0 = blockIdx.y * 128, col0 = blockIdx.x * 64;
    int mbase = (wid & 3) * 32, nbase = (wid >> 2) * 32;
    int sar = tid >> 1, sah = (tid & 1) * 8;
    int sbk = tid >> 4, sbc = (tid & 15) * 4;
    int arow = row0 + sar;
    int ab = arow >> 11, as = arow & 2047;
    size_t abase = ((size_t)ab * Hn * Sn + as) * HDn;   // + head*Sn*HDn + hd
    const float* Bptr = W + (size_t)sbk * N + col0 + sbc;
    int a_row = lane & 15;
    int a_colb = (lane >> 4) * 16;
    int b_row = (lane & 7) + ((lane >> 4) << 3);
    int b_colb = (lane & 8) ? 16 : 0;

    float acc[2][4][4] = {};

    {
        int c = sah;   // k0 = 0
        const float* src = g_att + abase + (size_t)(c >> 6) * Sn * HDn + (c & 63);
        float4 u = *(const float4*)src;
        float4 v = *(const float4*)(src + 4);
        uint32_t ph[4], pl[4];
        split2(u.x, u.y, ph[0], pl[0]); split2(u.z, u.w, ph[1], pl[1]);
        split2(v.x, v.y, ph[2], pl[2]); split2(v.z, v.w, ph[3], pl[3]);
        *(uint4*)&Ah[0][sar][sah] = make_uint4(ph[0], ph[1], ph[2], ph[3]);
        *(uint4*)&Al[0][sar][sah] = make_uint4(pl[0], pl[1], pl[2], pl[3]);
        float4 w = *(const float4*)Bptr;
        float wf[4] = {w.x, w.y, w.z, w.w};
        #pragma unroll
        for (int j = 0; j < 4; j++) {
            __nv_bfloat16 h, l; split1(wf[j], h, l);
            Bh[0][sbc + j][sbk] = h; Bl[0][sbc + j][sbk] = l;
        }
    }
    __syncthreads();

    const int T = K / 16;
    for (int t = 0; t < T; t++) {
        int buf = t & 1;
        float4 na0, na1, nb;
        if (t + 1 < T) {
            int c = (t + 1) * 16 + sah;
            const float* src = g_att + abase + (size_t)(c >> 6) * Sn * HDn + (c & 63);
            na0 = *(const float4*)src;
            na1 = *(const float4*)(src + 4);
            nb  = *(const float4*)(Bptr + (size_t)(t + 1) * 16 * N);
        }
        uint32_t ahf[2][4], alf[2][4], bhf[4][2], blf[4][2];
        #pragma unroll
        for (int i = 0; i < 2; i++) {
            uint32_t a0 = s2u(&Ah[buf][mbase + i * 16 + a_row][0]) + a_colb;
            ldsm4(ahf[i][0], ahf[i][1], ahf[i][2], ahf[i][3], a0);
            uint32_t a1 = s2u(&Al[buf][mbase + i * 16 + a_row][0]) + a_colb;
            ldsm4(alf[i][0], alf[i][1], alf[i][2], alf[i][3], a1);
        }
        #pragma unroll
        for (int jg = 0; jg < 2; jg++) {
            uint32_t r0, r1, r2, r3;
            uint32_t ba = s2u(&Bh[buf][nbase + jg * 16 + b_row][0]) + b_colb;
            ldsm4(r0, r1, r2, r3, ba);
            bhf[jg * 2][0] = r0; bhf[jg * 2][1] = r1;
            bhf[jg * 2 + 1][0] = r2; bhf[jg * 2 + 1][1] = r3;
            uint32_t bb = s2u(&Bl[buf][nbase + jg * 16 + b_row][0]) + b_colb;
            ldsm4(r0, r1, r2, r3, bb);
            blf[jg * 2][0] = r0; blf[jg * 2][1] = r1;
            blf[jg * 2 + 1][0] = r2; blf[jg * 2 + 1][1] = r3;
        }
        #pragma unroll
        for (int i = 0; i < 2; i++)
            #pragma unroll
            for (int j = 0; j < 4; j++) {
                MMA(acc[i][j], ahf[i], bhf[j]);
                MMA(acc[i][j], ahf[i], blf[j]);
                MMA(acc[i][j], alf[i], bhf[j]);
            }
        if (t + 1 < T) {
            int nbuf = buf ^ 1;
            uint32_t ph[4], pl[4];
            split2(na0.x, na0.y, ph[0], pl[0]); split2(na0.z, na0.w, ph[1], pl[1]);
            split2(na1.x, na1.y, ph[2], pl[2]); split2(na1.z, na1.w, ph[3], pl[3]);
            *(uint4*)&Ah[nbuf][sar][sah] = make_uint4(ph[0], ph[1], ph[2], ph[3]);
            *(uint4*)&Al[nbuf][sar][sah] = make_uint4(pl[0], pl[1], pl[2], pl[3]);
            float wf[4] = {nb.x, nb.y, nb.z, nb.w};
            #pragma unroll
            for (int j = 0; j < 4; j++) {
                __nv_bfloat16 h, l; split1(wf[j], h, l);
                Bh[nbuf][sbc + j][sbk] = h; Bl[nbuf][sbc + j][sbk] = l;
            }
        }
        __syncthreads();
    }

    #pragma unroll
    for (int i = 0; i < 2; i++) {
        #pragma unroll
        for (int j = 0; j < 4; j++) {
            int rr = row0 + mbase + i * 16 + (lane >> 2);
            int cc = col0 + nbase + j * 8 + (lane & 3) * 2;
            #pragma unroll
            for (int half = 0; half < 2; half++) {
                int r = rr + half * 8;
                out[(size_t)r * N + cc]     = acc[i][j][half * 2 + 0] + bias[cc];
                out[(size_t)r * N + cc + 1] = acc[i][j][half * 2 + 1] + bias[cc + 1];
            }
        }
    }
}

// ---------------------------------------------------------------------------
extern "C" void kernel_launch(void* const* d_in, const int* in_sizes, int n_in,
                              void* d_out, int out_size) {
    (void)in_sizes; (void)n_in; (void)out_size;
    const float* hs     = (const float*)d_in[0];
    const float* mask   = (const float*)d_in[1];
    const float* w_attn = (const float*)d_in[2];
    const float* b_attn = (const float*)d_in[3];
    const float* w_proj = (const float*)d_in[4];
    const float* b_proj = (const float*)d_in[5];

    float* attn_out = (float*)d_out;                          // [B,S,D]
    float* weights  = (float*)d_out + (size_t)Bn * Sn * Dn;   // [B,H,S,S]

    qkv_gemm<<<dim3(N3D / 64, BSn / 128), 256>>>(hs, w_attn, b_attn);
    scores_kernel<<<dim3(272, Bn * Hn), 256>>>(mask, weights);
    softmax_kernel<<<dim3(Bn * Hn * Sn), 256>>>(weights);
    av_kernel<<<dim3(Sn / 128, Bn * Hn), 256>>>(weights);
    proj_gemm<<<dim3(Dn / 64, BSn / 128), 256>>>(w_proj, b_proj, attn_out);
}

// round 4
// speedup vs baseline: 2.2901x; 1.3577x over previous
#include <cuda_runtime.h>
#include <cuda_bf16.h>
#include <math.h>
#include <stdint.h>

#define Bn 2
#define Sn 2048
#define Dn 1024
#define Hn 16
#define HDn 64
#define BSn (Bn*Sn)      // 4096
#define N3D (3*Dn)       // 3072
#define NQKV (Bn*Hn*Sn*HDn)

#define STAGES 4
#define STG_BYTES 18432          // A(hi+lo): 2*6144, B(hi+lo): 2*3072
#define SMEM_TOTAL (STAGES*STG_BYTES)   // 73728

// ---------------- bf16 hi/lo scratch (device globals) ----------------
__device__ __nv_bfloat16 s_hs_h[BSn*Dn],  s_hs_l[BSn*Dn];
__device__ __nv_bfloat16 s_wa_h[N3D*Dn],  s_wa_l[N3D*Dn];   // transposed [N][K]
__device__ __nv_bfloat16 s_wp_h[Dn*Dn],   s_wp_l[Dn*Dn];    // transposed [N][K]
__device__ __nv_bfloat16 g_q_h[NQKV], g_q_l[NQKV];          // [bh][s][hd]
__device__ __nv_bfloat16 g_k_h[NQKV], g_k_l[NQKV];          // [bh][s][hd]
__device__ __nv_bfloat16 g_v_h[NQKV], g_v_l[NQKV];          // [bh][hd][s] (transposed)
__device__ __nv_bfloat16 g_att_h[NQKV], g_att_l[NQKV];      // [bh][s][hd]
__device__ __nv_bfloat16 g_w_h[(size_t)Bn*Hn*Sn*Sn];        // split softmax weights
__device__ __nv_bfloat16 g_w_l[(size_t)Bn*Hn*Sn*Sn];

// ---------------- helpers ----------------
__device__ __forceinline__ uint32_t s2u(const void* p) {
    return (uint32_t)__cvta_generic_to_shared(p);
}
__device__ __forceinline__ void ldsm4(uint32_t& r0, uint32_t& r1, uint32_t& r2,
                                      uint32_t& r3, uint32_t a) {
    asm volatile("ldmatrix.sync.aligned.m8n8.x4.shared.b16 {%0,%1,%2,%3},[%4];"
                 : "=r"(r0), "=r"(r1), "=r"(r2), "=r"(r3) : "r"(a));
}
#define MMA(c, a, b) asm volatile( \
    "mma.sync.aligned.m16n8k16.row.col.f32.bf16.bf16.f32 " \
    "{%0,%1,%2,%3},{%4,%5,%6,%7},{%8,%9},{%0,%1,%2,%3};" \
    : "+f"((c)[0]), "+f"((c)[1]), "+f"((c)[2]), "+f"((c)[3]) \
    : "r"((a)[0]), "r"((a)[1]), "r"((a)[2]), "r"((a)[3]), "r"((b)[0]), "r"((b)[1]))

__device__ __forceinline__ void cpa16(uint32_t dst, const void* src) {
    asm volatile("cp.async.cg.shared.global [%0], [%1], 16;" :: "r"(dst), "l"(src));
}
#define CP_COMMIT() asm volatile("cp.async.commit_group;")
#define CP_WAIT2()  asm volatile("cp.async.wait_group 2;")

// split pair (x,y) -> packed bf16x2 hi and lo (mem order: x = low half)
__device__ __forceinline__ void split2(float x, float y, uint32_t& ph, uint32_t& pl) {
    uint32_t h;
    asm("cvt.rn.bf16x2.f32 %0, %1, %2;" : "=r"(h) : "f"(y), "f"(x));
    float hx = __uint_as_float(h << 16);
    float hy = __uint_as_float(h & 0xffff0000u);
    ph = h;
    asm("cvt.rn.bf16x2.f32 %0, %1, %2;" : "=r"(pl) : "f"(y - hy), "f"(x - hx));
}
__device__ __forceinline__ void split1(float x, __nv_bfloat16& h, __nv_bfloat16& l) {
    h = __float2bfloat16(x);
    l = __float2bfloat16(x - __bfloat162float(h));
}

// stage layout (byte offsets inside one STG_BYTES stage):
//   Ah: 0       (128 rows x 24 halves)  Al: +6144
//   Bh: +12288  (64 rows x 24 halves)   Bl: +15360  (Bl = Bh + 3072)
__device__ __forceinline__ void compute_stage(uint32_t stg, float acc[2][4][4],
    int mbase, int nbase, int a_row, int a_colb, int b_row, int b_colb) {
    uint32_t ahf[2][4], alf[2][4], bhf[4][2], blf[4][2];
    #pragma unroll
    for (int i = 0; i < 2; i++) {
        uint32_t r = stg + (uint32_t)(mbase + i * 16 + a_row) * 48 + a_colb;
        ldsm4(ahf[i][0], ahf[i][1], ahf[i][2], ahf[i][3], r);
        ldsm4(alf[i][0], alf[i][1], alf[i][2], alf[i][3], r + 6144);
    }
    #pragma unroll
    for (int jg = 0; jg < 2; jg++) {
        uint32_t r = stg + 12288 + (uint32_t)(nbase + jg * 16 + b_row) * 48 + b_colb;
        uint32_t r0, r1, r2, r3;
        ldsm4(r0, r1, r2, r3, r);
        bhf[jg * 2][0] = r0; bhf[jg * 2][1] = r1;
        bhf[jg * 2 + 1][0] = r2; bhf[jg * 2 + 1][1] = r3;
        ldsm4(r0, r1, r2, r3, r + 3072);
        blf[jg * 2][0] = r0; blf[jg * 2][1] = r1;
        blf[jg * 2 + 1][0] = r2; blf[jg * 2 + 1][1] = r3;
    }
    #pragma unroll
    for (int i = 0; i < 2; i++)
        #pragma unroll
        for (int j = 0; j < 4; j++) {
            MMA(acc[i][j], ahf[i], bhf[j]);
            MMA(acc[i][j], ahf[i], blf[j]);
            MMA(acc[i][j], alf[i], bhf[j]);
        }
}

// ---------------------------------------------------------------------------
// Kernel 0: one-shot split of inputs (hs straight; w_attn/w_proj transposed).
// ---------------------------------------------------------------------------
__global__ __launch_bounds__(256) void split_inputs(const float* __restrict__ hs,
                                                    const float* __restrict__ wa,
                                                    const float* __restrict__ wp) {
    const int NHS = BSn * Dn;     // 4194304
    const int NWA = Dn * N3D;     // 3145728
    const int NWP = Dn * Dn;      // 1048576
    int i = blockIdx.x * 256 + threadIdx.x;
    if (i < NHS) {
        __nv_bfloat16 h, l; split1(hs[i], h, l);
        s_hs_h[i] = h; s_hs_l[i] = l;
    } else if (i < NHS + NWA) {
        int j = i - NHS;             // out idx: n*1024 + k
        int n = j >> 10, k = j & 1023;
        __nv_bfloat16 h, l; split1(wa[k * N3D + n], h, l);
        s_wa_h[j] = h; s_wa_l[j] = l;
    } else if (i < NHS + NWA + NWP) {
        int j = i - NHS - NWA;
        int n = j >> 10, k = j & 1023;
        __nv_bfloat16 h, l; split1(wp[k * Dn + n], h, l);
        s_wp_h[j] = h; s_wp_l[j] = l;
    }
}

// ---------------------------------------------------------------------------
// Kernel 1: QKV projection (bf16 pipeline). Epilogue scatters split q/k/v.
// ---------------------------------------------------------------------------
__global__ __launch_bounds__(256, 2) void qkv_gemm(const float* __restrict__ bias) {
    extern __shared__ __align__(16) char dynsmem[];
    const uint32_t smb = s2u(dynsmem);
    const int K = 1024;
    int tid = threadIdx.x, lane = tid & 31, wid = tid >> 5;
    int row0 = blockIdx.y * 128, col0 = blockIdx.x * 64;
    int mbase = (wid & 3) * 32, nbase = (wid >> 2) * 32;
    int sar = tid >> 1, sah = (tid & 1) * 8;
    uint32_t a_off = (uint32_t)(sar * 24 + sah) * 2;
    int sbr = (tid & 127) >> 1, sbs = (tid & 1) * 8;
    uint32_t b_off = (uint32_t)(sbr * 24 + sbs) * 2;
    const __nv_bfloat16* gAh = s_hs_h + (size_t)(row0 + sar) * K + sah;
    const __nv_bfloat16* gAl = s_hs_l + (size_t)(row0 + sar) * K + sah;
    const __nv_bfloat16* gBh = s_wa_h + (size_t)(col0 + sbr) * K + sbs;
    const __nv_bfloat16* gBl = s_wa_l + (size_t)(col0 + sbr) * K + sbs;
    int a_row = lane & 15, a_colb = (lane >> 4) * 16;
    int b_row = (lane & 7) + ((lane >> 4) << 3);
    int b_colb = (lane & 8) ? 16 : 0;

    float acc[2][4][4] = {};
    const int T = K / 16;

    #define QISSUE(t) do { int sl = (t) & 3; uint32_t st = smb + sl * STG_BYTES; \
        cpa16(st + a_off, gAh + (t) * 16); cpa16(st + 6144 + a_off, gAl + (t) * 16); \
        if (tid < 128) { cpa16(st + 12288 + b_off, gBh + (t) * 16); \
                         cpa16(st + 15360 + b_off, gBl + (t) * 16); } } while (0)

    for (int s = 0; s < STAGES - 1 && s < T; s++) { QISSUE(s); CP_COMMIT(); }
    for (int t = 0; t < T; t++) {
        CP_WAIT2();
        __syncthreads();
        if (t + STAGES - 1 < T) QISSUE(t + STAGES - 1);
        CP_COMMIT();
        compute_stage(smb + (t & 3) * STG_BYTES, acc, mbase, nbase,
                      a_row, a_colb, b_row, b_colb);
    }
    #undef QISSUE

    #pragma unroll
    for (int i = 0; i < 2; i++) {
        #pragma unroll
        for (int j = 0; j < 4; j++) {
            int rr = row0 + mbase + i * 16 + (lane >> 2);
            int cc = col0 + nbase + j * 8 + (lane & 3) * 2;
            #pragma unroll
            for (int half = 0; half < 2; half++) {
                int r = rr + half * 8;
                int b = r >> 11, s = r & 2047;
                float v0 = acc[i][j][half * 2 + 0] + bias[cc];
                float v1 = acc[i][j][half * 2 + 1] + bias[cc + 1];
                uint32_t ph, pl; split2(v0, v1, ph, pl);
                int which = cc >> 10;
                int dcol = cc & 1023;
                int h = dcol >> 6, hd = dcol & 63;
                int bh = b * Hn + h;
                if (which == 0) {
                    size_t idx = ((size_t)bh * Sn + s) * HDn + hd;
                    *(uint32_t*)&g_q_h[idx] = ph; *(uint32_t*)&g_q_l[idx] = pl;
                } else if (which == 1) {
                    size_t idx = ((size_t)bh * Sn + s) * HDn + hd;
                    *(uint32_t*)&g_k_h[idx] = ph; *(uint32_t*)&g_k_l[idx] = pl;
                } else {   // v: transposed [bh][hd][s]
                    size_t i0 = ((size_t)bh * HDn + hd) * Sn + s;
                    size_t i1 = ((size_t)bh * HDn + hd + 1) * Sn + s;
                    ((uint16_t*)g_v_h)[i0] = (uint16_t)(ph & 0xffff);
                    ((uint16_t*)g_v_h)[i1] = (uint16_t)(ph >> 16);
                    ((uint16_t*)g_v_l)[i0] = (uint16_t)(pl & 0xffff);
                    ((uint16_t*)g_v_l)[i1] = (uint16_t)(pl >> 16);
                }
            }
        }
    }
}

// ---------------------------------------------------------------------------
// Kernel 2: raw scores, lower-tri 128x64 tiles, K=64 (bf16 pipeline).
// ---------------------------------------------------------------------------
__global__ __launch_bounds__(256, 2) void scores_kernel(const float* __restrict__ mask,
                                                        float* __restrict__ Wout) {
    extern __shared__ __align__(16) char dynsmem[];
    const uint32_t smb = s2u(dynsmem);
    int idx = blockIdx.x;
    int qb = (int)((sqrtf(4.0f * idx + 1.0f) - 1.0f) * 0.5f);
    while ((qb + 1) * (qb + 2) <= idx) qb++;
    while (qb * (qb + 1) > idx) qb--;
    int kb = idx - qb * (qb + 1);
    int bh = blockIdx.y;
    int bb = bh >> 4;
    int tid = threadIdx.x, lane = tid & 31, wid = tid >> 5;
    int row0 = qb * 128, col0 = kb * 64;
    int mbase = (wid & 3) * 32, nbase = (wid >> 2) * 32;
    int sar = tid >> 1, sah = (tid & 1) * 8;
    uint32_t a_off = (uint32_t)(sar * 24 + sah) * 2;
    int sbr = (tid & 127) >> 1, sbs = (tid & 1) * 8;
    uint32_t b_off = (uint32_t)(sbr * 24 + sbs) * 2;
    const __nv_bfloat16* gAh = g_q_h + ((size_t)bh * Sn + row0 + sar) * HDn + sah;
    const __nv_bfloat16* gAl = g_q_l + ((size_t)bh * Sn + row0 + sar) * HDn + sah;
    const __nv_bfloat16* gBh = g_k_h + ((size_t)bh * Sn + col0 + sbr) * HDn + sbs;
    const __nv_bfloat16* gBl = g_k_l + ((size_t)bh * Sn + col0 + sbr) * HDn + sbs;
    int a_row = lane & 15, a_colb = (lane >> 4) * 16;
    int b_row = (lane & 7) + ((lane >> 4) << 3);
    int b_colb = (lane & 8) ? 16 : 0;

    float acc[2][4][4] = {};
    const int T = HDn / 16;   // 4

    #define SISSUE(t) do { int sl = (t) & 3; uint32_t st = smb + sl * STG_BYTES; \
        cpa16(st + a_off, gAh + (t) * 16); cpa16(st + 6144 + a_off, gAl + (t) * 16); \
        if (tid < 128) { cpa16(st + 12288 + b_off, gBh + (t) * 16); \
                         cpa16(st + 15360 + b_off, gBl + (t) * 16); } } while (0)

    for (int s = 0; s < STAGES - 1 && s < T; s++) { SISSUE(s); CP_COMMIT(); }
    for (int t = 0; t < T; t++) {
        CP_WAIT2();
        __syncthreads();
        if (t + STAGES - 1 < T) SISSUE(t + STAGES - 1);
        CP_COMMIT();
        compute_stage(smb + (t & 3) * STG_BYTES, acc, mbase, nbase,
                      a_row, a_colb, b_row, b_colb);
    }
    #undef SISSUE

    const float scale = 0.125f;
    #pragma unroll
    for (int i = 0; i < 2; i++) {
        #pragma unroll
        for (int j = 0; j < 4; j++) {
            int rr = row0 + mbase + i * 16 + (lane >> 2);
            int cc = col0 + nbase + j * 8 + (lane & 3) * 2;
            #pragma unroll
            for (int half = 0; half < 2; half++) {
                int r = rr + half * 8;
                float* orow = Wout + ((size_t)bh * Sn + r) * Sn;
                orow[cc]     = acc[i][j][half * 2 + 0] * scale + mask[bb * Sn + cc];
                orow[cc + 1] = acc[i][j][half * 2 + 1] * scale + mask[bb * Sn + cc + 1];
            }
        }
    }
}

// ---------------------------------------------------------------------------
// Kernel 3: row softmax; writes fp32 weights (full row) + split bf16 weights
// over the causal band [0, blockend) where blockend = ((q>>7)+1)*128.
// ---------------------------------------------------------------------------
__global__ __launch_bounds__(256) void softmax_kernel(float* __restrict__ Wm) {
    __shared__ float buf[Sn];
    __shared__ float red[8];
    int row = blockIdx.x;
    int q = row & (Sn - 1);
    int len = q + 1;
    int blockend = ((q >> 7) + 1) << 7;
    float* wrow = Wm + (size_t)row * Sn;
    size_t wb = (size_t)row * Sn;
    int tid = threadIdx.x;
    int lane = tid & 31, warp = tid >> 5;

    float mx = -1e30f;
    for (int c = tid; c < len; c += 256) {
        float v = wrow[c];
        buf[c] = v;
        mx = fmaxf(mx, v);
    }
    #pragma unroll
    for (int o = 16; o > 0; o >>= 1) mx = fmaxf(mx, __shfl_xor_sync(0xffffffffu, mx, o));
    if (lane == 0) red[warp] = mx;
    __syncthreads();
    if (tid < 32) {
        float t = (tid < 8) ? red[tid] : -1e30f;
        #pragma unroll
        for (int o = 4; o > 0; o >>= 1) t = fmaxf(t, __shfl_xor_sync(0xffffffffu, t, o));
        if (tid == 0) red[0] = t;
    }
    __syncthreads();
    mx = red[0];
    __syncthreads();

    float sum = 0.0f;
    for (int c = tid; c < len; c += 256) {
        float e = __expf(buf[c] - mx);
        buf[c] = e;
        sum += e;
    }
    #pragma unroll
    for (int o = 16; o > 0; o >>= 1) sum += __shfl_xor_sync(0xffffffffu, sum, o);
    if (lane == 0) red[warp] = sum;
    __syncthreads();
    if (tid < 32) {
        float t = (tid < 8) ? red[tid] : 0.0f;
        #pragma unroll
        for (int o = 4; o > 0; o >>= 1) t += __shfl_xor_sync(0xffffffffu, t, o);
        if (tid == 0) red[0] = t;
    }
    __syncthreads();
    float inv = 1.0f / red[0];

    for (int c = tid * 2; c < Sn; c += 512) {
        float v0 = (c < len) ? buf[c] * inv : 0.0f;
        float v1 = (c + 1 < len) ? buf[c + 1] * inv : 0.0f;
        wrow[c] = v0;
        wrow[c + 1] = v1;
        if (c < blockend) {
            uint32_t ph, pl; split2(v0, v1, ph, pl);
            *(uint32_t*)&g_w_h[wb + c] = ph;
            *(uint32_t*)&g_w_l[wb + c] = pl;
        }
    }
}

// ---------------------------------------------------------------------------
// Kernel 4: attn_heads = weights @ V per (b,h). Causal k-loop, bf16 pipeline.
// Epilogue writes split att.
// ---------------------------------------------------------------------------
__global__ __launch_bounds__(256, 2) void av_kernel() {
    extern __shared__ __align__(16) char dynsmem[];
    const uint32_t smb = s2u(dynsmem);
    int qb = gridDim.x - 1 - blockIdx.x;   // longest first
    int bh = blockIdx.y;
    int tid = threadIdx.x, lane = tid & 31, wid = tid >> 5;
    int row0 = qb * 128;
    int mbase = (wid & 3) * 32, nbase = (wid >> 2) * 32;
    int sar = tid >> 1, sah = (tid & 1) * 8;
    uint32_t a_off = (uint32_t)(sar * 24 + sah) * 2;
    int sbr = (tid & 127) >> 1, sbs = (tid & 1) * 8;
    uint32_t b_off = (uint32_t)(sbr * 24 + sbs) * 2;
    const __nv_bfloat16* gAh = g_w_h + (size_t)bh * Sn * Sn + (size_t)(row0 + sar) * Sn + sah;
    const __nv_bfloat16* gAl = g_w_l + (size_t)bh * Sn * Sn + (size_t)(row0 + sar) * Sn + sah;
    const __nv_bfloat16* gBh = g_v_h + ((size_t)bh * HDn + sbr) * Sn + sbs;
    const __nv_bfloat16* gBl = g_v_l + ((size_t)bh * HDn + sbr) * Sn + sbs;
    int a_row = lane & 15, a_colb = (lane >> 4) * 16;
    int b_row = (lane & 7) + ((lane >> 4) << 3);
    int b_colb = (lane & 8) ? 16 : 0;

    float acc[2][4][4] = {};
    const int T = (qb + 1) * 8;

    #define AISSUE(t) do { int sl = (t) & 3; uint32_t st = smb + sl * STG_BYTES; \
        cpa16(st + a_off, gAh + (t) * 16); cpa16(st + 6144 + a_off, gAl + (t) * 16); \
        if (tid < 128) { cpa16(st + 12288 + b_off, gBh + (t) * 16); \
                         cpa16(st + 15360 + b_off, gBl + (t) * 16); } } while (0)

    for (int s = 0; s < STAGES - 1 && s < T; s++) { AISSUE(s); CP_COMMIT(); }
    for (int t = 0; t < T; t++) {
        CP_WAIT2();
        __syncthreads();
        if (t + STAGES - 1 < T) AISSUE(t + STAGES - 1);
        CP_COMMIT();
        compute_stage(smb + (t & 3) * STG_BYTES, acc, mbase, nbase,
                      a_row, a_colb, b_row, b_colb);
    }
    #undef AISSUE

    #pragma unroll
    for (int i = 0; i < 2; i++) {
        #pragma unroll
        for (int j = 0; j < 4; j++) {
            int rr = row0 + mbase + i * 16 + (lane >> 2);
            int cc = nbase + j * 8 + (lane & 3) * 2;
            #pragma unroll
            for (int half = 0; half < 2; half++) {
                int r = rr + half * 8;
                uint32_t ph, pl;
                split2(acc[i][j][half * 2 + 0], acc[i][j][half * 2 + 1], ph, pl);
                size_t idx = ((size_t)bh * Sn + r) * HDn + cc;
                *(uint32_t*)&g_att_h[idx] = ph;
                *(uint32_t*)&g_att_l[idx] = pl;
            }
        }
    }
}

// ---------------------------------------------------------------------------
// Kernel 5: output projection, head-transpose folded into A staging addresses.
// ---------------------------------------------------------------------------
__global__ __launch_bounds__(256, 2) void proj_gemm(const float* __restrict__ bias,
                                                    float* __restrict__ out) {
    extern __shared__ __align__(16) char dynsmem[];
    const uint32_t smb = s2u(dynsmem);
    const int K = 1024, N = 1024;
    int tid = threadIdx.x, lane = tid & 31, wid = tid >> 5;
    int row0 = blockIdx.y * 128, col0 = blockIdx.x * 64;
    int mbase = (wid & 3) * 32, nbase = (wid >> 2) * 32;
    int sar = tid >> 1, sah = (tid & 1) * 8;
    uint32_t a_off = (uint32_t)(sar * 24 + sah) * 2;
    int sbr = (tid & 127) >> 1, sbs = (tid & 1) * 8;
    uint32_t b_off = (uint32_t)(sbr * 24 + sbs) * 2;
    int arow = row0 + sar;
    int ab = arow >> 11, as = arow & 2047;
    size_t abase = ((size_t)ab * Hn * Sn + as) * HDn;
    const __nv_bfloat16* gBh = s_wp_h + (size_t)(col0 + sbr) * K + sbs;
    const __nv_bfloat16* gBl = s_wp_l + (size_t)(col0 + sbr) * K + sbs;
    int a_row = lane & 15, a_colb = (lane >> 4) * 16;
    int b_row = (lane & 7) + ((lane >> 4) << 3);
    int b_colb = (lane & 8) ? 16 : 0;

    float acc[2][4][4] = {};
    const int T = K / 16;

    #define PISSUE(t) do { int sl = (t) & 3; uint32_t st = smb + sl * STG_BYTES; \
        int c = (t) * 16 + sah; \
        size_t so = abase + (size_t)(c >> 6) * Sn * HDn + (c & 63); \
        cpa16(st + a_off, g_att_h + so); cpa16(st + 6144 + a_off, g_att_l + so); \
        if (tid < 128) { cpa16(st + 12288 + b_off, gBh + (t) * 16); \
                         cpa16(st + 15360 + b_off, gBl + (t) * 16); } } while (0)

    for (int s = 0; s < STAGES - 1 && s < T; s++) { PISSUE(s); CP_COMMIT(); }
    for (int t = 0; t < T; t++) {
        CP_WAIT2();
        __syncthreads();
        if (t + STAGES - 1 < T) PISSUE(t + STAGES - 1);
        CP_COMMIT();
        compute_stage(smb + (t & 3) * STG_BYTES, acc, mbase, nbase,
                      a_row, a_colb, b_row, b_colb);
    }
    #undef PISSUE

    #pragma unroll
    for (int i = 0; i < 2; i++) {
        #pragma unroll
        for (int j = 0; j < 4; j++) {
            int rr = row0 + mbase + i * 16 + (lane >> 2);
            int cc = col0 + nbase + j * 8 + (lane & 3) * 2;
            #pragma unroll
            for (int half = 0; half < 2; half++) {
                int r = rr + half * 8;
                out[(size_t)r * N + cc]     = acc[i][j][half * 2 + 0] + bias[cc];
                out[(size_t)r * N + cc + 1] = acc[i][j][half * 2 + 1] + bias[cc + 1];
            }
        }
    }
}

// ---------------------------------------------------------------------------
extern "C" void kernel_launch(void* const* d_in, const int* in_sizes, int n_in,
                              void* d_out, int out_size) {
    (void)in_sizes; (void)n_in; (void)out_size;
    const float* hs     = (const float*)d_in[0];
    const float* mask   = (const float*)d_in[1];
    const float* w_attn = (const float*)d_in[2];
    const float* b_attn = (const float*)d_in[3];
    const float* w_proj = (const float*)d_in[4];
    const float* b_proj = (const float*)d_in[5];

    float* attn_out = (float*)d_out;                          // [B,S,D]
    float* weights  = (float*)d_out + (size_t)Bn * Sn * Dn;   // [B,H,S,S]

    cudaFuncSetAttribute(qkv_gemm,      cudaFuncAttributeMaxDynamicSharedMemorySize, SMEM_TOTAL);
    cudaFuncSetAttribute(scores_kernel, cudaFuncAttributeMaxDynamicSharedMemorySize, SMEM_TOTAL);
    cudaFuncSetAttribute(av_kernel,     cudaFuncAttributeMaxDynamicSharedMemorySize, SMEM_TOTAL);
    cudaFuncSetAttribute(proj_gemm,     cudaFuncAttributeMaxDynamicSharedMemorySize, SMEM_TOTAL);

    const int NSPLIT = BSn * Dn + Dn * N3D + Dn * Dn;   // 8388608
    split_inputs<<<NSPLIT / 256, 256>>>(hs, w_attn, w_proj);
    qkv_gemm<<<dim3(N3D / 64, BSn / 128), 256, SMEM_TOTAL>>>(b_attn);
    scores_kernel<<<dim3(272, Bn * Hn), 256, SMEM_TOTAL>>>(mask, weights);
    softmax_kernel<<<dim3(Bn * Hn * Sn), 256>>>(weights);
    av_kernel<<<dim3(Sn / 128, Bn * Hn), 256, SMEM_TOTAL>>>();
    proj_gemm<<<dim3(Dn / 64, BSn / 128), 256, SMEM_TOTAL>>>(b_proj, attn_out);
}

// round 5
// speedup vs baseline: 2.4582x; 1.0734x over previous
#include <cuda_runtime.h>
#include <cuda_bf16.h>
#include <math.h>
#include <stdint.h>

#define Bn 2
#define Sn 2048
#define Dn 1024
#define Hn 16
#define HDn 64
#define BSn (Bn*Sn)      // 4096
#define N3D (3*Dn)       // 3072
#define NQKV (Bn*Hn*Sn*HDn)

// stage layouts:
//  wide (128n) kernels: Ah 0 (6144B) Al 6144 Bh 12288 (6144B) Bl 18432 -> 24576/stage
//  av   (64n)  kernel : Ah 0        Al 6144 Bh 12288 (3072B) Bl 15360 -> 18432/stage
#define STG_W 24576
#define STG_AV 18432
#define STAGES 4
#define SMEM_W  (STAGES*STG_W)    // 98304
#define SMEM_AV (STAGES*STG_AV)   // 73728

// ---------------- bf16 hi/lo scratch (device globals) ----------------
__device__ __nv_bfloat16 s_hs_h[BSn*Dn],  s_hs_l[BSn*Dn];
__device__ __nv_bfloat16 s_wa_h[N3D*Dn],  s_wa_l[N3D*Dn];   // transposed [N][K]
__device__ __nv_bfloat16 s_wp_h[Dn*Dn],   s_wp_l[Dn*Dn];    // transposed [N][K]
__device__ __nv_bfloat16 g_q_h[NQKV], g_q_l[NQKV];          // [bh][s][hd]
__device__ __nv_bfloat16 g_k_h[NQKV], g_k_l[NQKV];          // [bh][s][hd]
__device__ __nv_bfloat16 g_v_h[NQKV], g_v_l[NQKV];          // [bh][hd][s] (transposed)
__device__ __nv_bfloat16 g_att_h[NQKV], g_att_l[NQKV];      // [bh][s][hd]
__device__ __nv_bfloat16 g_w_h[(size_t)Bn*Hn*Sn*Sn];        // split softmax weights
__device__ __nv_bfloat16 g_w_l[(size_t)Bn*Hn*Sn*Sn];

// ---------------- helpers ----------------
__device__ __forceinline__ uint32_t s2u(const void* p) {
    return (uint32_t)__cvta_generic_to_shared(p);
}
__device__ __forceinline__ void ldsm4(uint32_t& r0, uint32_t& r1, uint32_t& r2,
                                      uint32_t& r3, uint32_t a) {
    asm volatile("ldmatrix.sync.aligned.m8n8.x4.shared.b16 {%0,%1,%2,%3},[%4];"
                 : "=r"(r0), "=r"(r1), "=r"(r2), "=r"(r3) : "r"(a));
}
#define MMA(c, a, b) asm volatile( \
    "mma.sync.aligned.m16n8k16.row.col.f32.bf16.bf16.f32 " \
    "{%0,%1,%2,%3},{%4,%5,%6,%7},{%8,%9},{%0,%1,%2,%3};" \
    : "+f"((c)[0]), "+f"((c)[1]), "+f"((c)[2]), "+f"((c)[3]) \
    : "r"((a)[0]), "r"((a)[1]), "r"((a)[2]), "r"((a)[3]), "r"((b)[0]), "r"((b)[1]))

__device__ __forceinline__ void cpa16(uint32_t dst, const void* src) {
    asm volatile("cp.async.cg.shared.global [%0], [%1], 16;" :: "r"(dst), "l"(src));
}
#define CP_COMMIT() asm volatile("cp.async.commit_group;")
#define CP_WAIT2()  asm volatile("cp.async.wait_group 2;")

// split pair (x,y) -> packed bf16x2 hi and lo (mem order: x = low half)
__device__ __forceinline__ void split2(float x, float y, uint32_t& ph, uint32_t& pl) {
    uint32_t h;
    asm("cvt.rn.bf16x2.f32 %0, %1, %2;" : "=r"(h) : "f"(y), "f"(x));
    float hx = __uint_as_float(h << 16);
    float hy = __uint_as_float(h & 0xffff0000u);
    ph = h;
    asm("cvt.rn.bf16x2.f32 %0, %1, %2;" : "=r"(pl) : "f"(y - hy), "f"(x - hx));
}
__device__ __forceinline__ void split1(float x, __nv_bfloat16& h, __nv_bfloat16& l) {
    h = __float2bfloat16(x);
    l = __float2bfloat16(x - __bfloat162float(h));
}

// compute one k16 stage. A always 128 rows (hi at stg+0, lo at +6144, pitch 48B).
// B hi at stg+12288, lo at +12288+BLO. 4 m-frags; NBF n-frags of 8.
template<int NBF, int BLO>
__device__ __forceinline__ void cstage(uint32_t stg, float acc[4][NBF][4],
    int mbase, int nbase, int a_row, int a_colb, int b_row, int b_colb) {
    uint32_t bhf[NBF][2], blf[NBF][2];
    #pragma unroll
    for (int jg = 0; jg < NBF / 2; jg++) {
        uint32_t r = stg + 12288u + (uint32_t)(nbase + jg * 16 + b_row) * 48 + b_colb;
        uint32_t r0, r1, r2, r3;
        ldsm4(r0, r1, r2, r3, r);
        bhf[jg * 2][0] = r0; bhf[jg * 2][1] = r1;
        bhf[jg * 2 + 1][0] = r2; bhf[jg * 2 + 1][1] = r3;
        ldsm4(r0, r1, r2, r3, r + BLO);
        blf[jg * 2][0] = r0; blf[jg * 2][1] = r1;
        blf[jg * 2 + 1][0] = r2; blf[jg * 2 + 1][1] = r3;
    }
    #pragma unroll
    for (int i = 0; i < 4; i++) {
        uint32_t ah[4], al[4];
        uint32_t r = stg + (uint32_t)(mbase + i * 16 + a_row) * 48 + a_colb;
        ldsm4(ah[0], ah[1], ah[2], ah[3], r);
        ldsm4(al[0], al[1], al[2], al[3], r + 6144);
        #pragma unroll
        for (int j = 0; j < NBF; j++) {
            MMA(acc[i][j], ah, bhf[j]);
            MMA(acc[i][j], ah, blf[j]);
            MMA(acc[i][j], al, bhf[j]);
        }
    }
}

// ---------------------------------------------------------------------------
// Kernel 0a: split hidden states (contiguous, float4 per thread).
// ---------------------------------------------------------------------------
__global__ __launch_bounds__(256) void split_hs(const float* __restrict__ hs) {
    int i = (blockIdx.x * 256 + threadIdx.x) * 4;
    float4 v = *(const float4*)&hs[i];
    uint32_t ph0, pl0, ph1, pl1;
    split2(v.x, v.y, ph0, pl0);
    split2(v.z, v.w, ph1, pl1);
    *(uint2*)&s_hs_h[i] = make_uint2(ph0, ph1);
    *(uint2*)&s_hs_l[i] = make_uint2(pl0, pl1);
}

// ---------------------------------------------------------------------------
// Kernel 0b: tiled transpose + split of a [K,N] weight -> hi/lo [N,K].
// ---------------------------------------------------------------------------
__global__ __launch_bounds__(256) void split_transpose(const float* __restrict__ in,
                                                       __nv_bfloat16* __restrict__ oh,
                                                       __nv_bfloat16* __restrict__ ol,
                                                       int K, int N) {
    __shared__ float t[32][33];
    int nb = blockIdx.x * 32, kb = blockIdx.y * 32;
    int tx = threadIdx.x & 31, ty = threadIdx.x >> 5;   // 32 x 8
    #pragma unroll
    for (int i = 0; i < 4; i++) {
        int r = ty + i * 8;
        t[r][tx] = in[(size_t)(kb + r) * N + nb + tx];
    }
    __syncthreads();
    #pragma unroll
    for (int i = 0; i < 4; i++) {
        int r = ty + i * 8;                 // n-local
        float v = t[tx][r];                 // k-local = tx
        __nv_bfloat16 h, l; split1(v, h, l);
        size_t o = (size_t)(nb + r) * K + kb + tx;
        oh[o] = h; ol[o] = l;
    }
}

// ---------------------------------------------------------------------------
// Kernel 1: QKV projection. block 128m x 128n, warp 64x32, 4-stage cp.async.
// ---------------------------------------------------------------------------
__global__ __launch_bounds__(256, 2) void qkv_gemm(const float* __restrict__ bias) {
    extern __shared__ __align__(16) char dynsmem[];
    const uint32_t smb = s2u(dynsmem);
    const int K = 1024;
    int tid = threadIdx.x, lane = tid & 31, wid = tid >> 5;
    int row0 = blockIdx.y * 128, col0 = blockIdx.x * 128;
    int mbase = (wid & 1) * 64, nbase = (wid >> 1) * 32;
    int sar = tid >> 1, sah = (tid & 1) * 8;
    uint32_t a_off = (uint32_t)(sar * 24 + sah) * 2;
    uint32_t b_off = a_off;                          // B also 128 rows
    const __nv_bfloat16* gAh = s_hs_h + (size_t)(row0 + sar) * K + sah;
    const __nv_bfloat16* gAl = s_hs_l + (size_t)(row0 + sar) * K + sah;
    const __nv_bfloat16* gBh = s_wa_h + (size_t)(col0 + sar) * K + sah;
    const __nv_bfloat16* gBl = s_wa_l + (size_t)(col0 + sar) * K + sah;
    int a_row = lane & 15, a_colb = (lane >> 4) * 16;
    int b_row = (lane & 7) + ((lane >> 4) << 3);
    int b_colb = (lane & 8) ? 16 : 0;

    float acc[4][4][4] = {};
    const int T = K / 16;

    #define QISSUE(t) do { uint32_t st = smb + ((t) & 3) * STG_W; \
        cpa16(st + a_off, gAh + (t) * 16); cpa16(st + 6144 + a_off, gAl + (t) * 16); \
        cpa16(st + 12288 + b_off, gBh + (t) * 16); \
        cpa16(st + 18432 + b_off, gBl + (t) * 16); } while (0)

    for (int s = 0; s < STAGES - 1; s++) { QISSUE(s); CP_COMMIT(); }
    for (int t = 0; t < T; t++) {
        CP_WAIT2();
        __syncthreads();
        if (t + STAGES - 1 < T) QISSUE(t + STAGES - 1);
        CP_COMMIT();
        cstage<4, 6144>(smb + (t & 3) * STG_W, acc, mbase, nbase,
                        a_row, a_colb, b_row, b_colb);
    }
    #undef QISSUE

    #pragma unroll
    for (int i = 0; i < 4; i++) {
        #pragma unroll
        for (int j = 0; j < 4; j++) {
            int rr = row0 + mbase + i * 16 + (lane >> 2);
            int cc = col0 + nbase + j * 8 + (lane & 3) * 2;
            #pragma unroll
            for (int half = 0; half < 2; half++) {
                int r = rr + half * 8;
                int b = r >> 11, s = r & 2047;
                float v0 = acc[i][j][half * 2 + 0] + bias[cc];
                float v1 = acc[i][j][half * 2 + 1] + bias[cc + 1];
                uint32_t ph, pl; split2(v0, v1, ph, pl);
                int which = cc >> 10;
                int dcol = cc & 1023;
                int h = dcol >> 6, hd = dcol & 63;
                int bh = b * Hn + h;
                if (which == 0) {
                    size_t idx = ((size_t)bh * Sn + s) * HDn + hd;
                    *(uint32_t*)&g_q_h[idx] = ph; *(uint32_t*)&g_q_l[idx] = pl;
                } else if (which == 1) {
                    size_t idx = ((size_t)bh * Sn + s) * HDn + hd;
                    *(uint32_t*)&g_k_h[idx] = ph; *(uint32_t*)&g_k_l[idx] = pl;
                } else {
                    size_t i0 = ((size_t)bh * HDn + hd) * Sn + s;
                    size_t i1 = ((size_t)bh * HDn + hd + 1) * Sn + s;
                    ((uint16_t*)g_v_h)[i0] = (uint16_t)(ph & 0xffff);
                    ((uint16_t*)g_v_h)[i1] = (uint16_t)(ph >> 16);
                    ((uint16_t*)g_v_l)[i0] = (uint16_t)(pl & 0xffff);
                    ((uint16_t*)g_v_l)[i1] = (uint16_t)(pl >> 16);
                }
            }
        }
    }
}

// ---------------------------------------------------------------------------
// Kernel 2: raw scores, lower-tri 128x128 tiles, K=64.
// ---------------------------------------------------------------------------
__global__ __launch_bounds__(256, 2) void scores_kernel(const float* __restrict__ mask,
                                                        float* __restrict__ Wout) {
    extern __shared__ __align__(16) char dynsmem[];
    const uint32_t smb = s2u(dynsmem);
    int idx = blockIdx.x;    // 0..135, tri pairs (qb,kb), kb<=qb, 16 qb values
    int qb = (int)((sqrtf(8.0f * idx + 1.0f) - 1.0f) * 0.5f);
    while ((qb + 1) * (qb + 2) / 2 <= idx) qb++;
    while (qb * (qb + 1) / 2 > idx) qb--;
    int kb = idx - qb * (qb + 1) / 2;
    int bh = blockIdx.y;
    int bb = bh >> 4;
    int tid = threadIdx.x, lane = tid & 31, wid = tid >> 5;
    int row0 = qb * 128, col0 = kb * 128;
    int mbase = (wid & 1) * 64, nbase = (wid >> 1) * 32;
    int sar = tid >> 1, sah = (tid & 1) * 8;
    uint32_t a_off = (uint32_t)(sar * 24 + sah) * 2;
    uint32_t b_off = a_off;
    const __nv_bfloat16* gAh = g_q_h + ((size_t)bh * Sn + row0 + sar) * HDn + sah;
    const __nv_bfloat16* gAl = g_q_l + ((size_t)bh * Sn + row0 + sar) * HDn + sah;
    const __nv_bfloat16* gBh = g_k_h + ((size_t)bh * Sn + col0 + sar) * HDn + sah;
    const __nv_bfloat16* gBl = g_k_l + ((size_t)bh * Sn + col0 + sar) * HDn + sah;
    int a_row = lane & 15, a_colb = (lane >> 4) * 16;
    int b_row = (lane & 7) + ((lane >> 4) << 3);
    int b_colb = (lane & 8) ? 16 : 0;

    float acc[4][4][4] = {};
    const int T = HDn / 16;   // 4

    #define SISSUE(t) do { uint32_t st = smb + ((t) & 3) * STG_W; \
        cpa16(st + a_off, gAh + (t) * 16); cpa16(st + 6144 + a_off, gAl + (t) * 16); \
        cpa16(st + 12288 + b_off, gBh + (t) * 16); \
        cpa16(st + 18432 + b_off, gBl + (t) * 16); } while (0)

    for (int s = 0; s < STAGES - 1 && s < T; s++) { SISSUE(s); CP_COMMIT(); }
    for (int t = 0; t < T; t++) {
        CP_WAIT2();
        __syncthreads();
        if (t + STAGES - 1 < T) SISSUE(t + STAGES - 1);
        CP_COMMIT();
        cstage<4, 6144>(smb + (t & 3) * STG_W, acc, mbase, nbase,
                        a_row, a_colb, b_row, b_colb);
    }
    #undef SISSUE

    const float scale = 0.125f;
    #pragma unroll
    for (int i = 0; i < 4; i++) {
        #pragma unroll
        for (int j = 0; j < 4; j++) {
            int rr = row0 + mbase + i * 16 + (lane >> 2);
            int cc = col0 + nbase + j * 8 + (lane & 3) * 2;
            #pragma unroll
            for (int half = 0; half < 2; half++) {
                int r = rr + half * 8;
                float* orow = Wout + ((size_t)bh * Sn + r) * Sn;
                orow[cc]     = acc[i][j][half * 2 + 0] * scale + mask[bb * Sn + cc];
                orow[cc + 1] = acc[i][j][half * 2 + 1] * scale + mask[bb * Sn + cc + 1];
            }
        }
    }
}

// ---------------------------------------------------------------------------
// Kernel 3: row softmax, float4 vectorized; writes fp32 weights + split bf16
// band [0, blockend).
// ---------------------------------------------------------------------------
__global__ __launch_bounds__(256) void softmax_kernel(float* __restrict__ Wm) {
    __shared__ float buf[Sn];
    __shared__ float red[8];
    int row = blockIdx.x;
    int q = row & (Sn - 1);
    int len = q + 1;
    int blockend = ((q >> 7) + 1) << 7;
    float* wrow = Wm + (size_t)row * Sn;
    size_t wb = (size_t)row * Sn;
    int tid = threadIdx.x;
    int lane = tid & 31, warp = tid >> 5;

    float mx = -1e30f;
    for (int c = tid * 4; c < blockend; c += 1024) {
        float4 v = *(const float4*)&wrow[c];
        *(float4*)&buf[c] = v;
        if (c + 3 < len) {
            mx = fmaxf(mx, fmaxf(fmaxf(v.x, v.y), fmaxf(v.z, v.w)));
        } else {
            if (c     < len) mx = fmaxf(mx, v.x);
            if (c + 1 < len) mx = fmaxf(mx, v.y);
            if (c + 2 < len) mx = fmaxf(mx, v.z);
            if (c + 3 < len) mx = fmaxf(mx, v.w);
        }
    }
    #pragma unroll
    for (int o = 16; o > 0; o >>= 1) mx = fmaxf(mx, __shfl_xor_sync(0xffffffffu, mx, o));
    if (lane == 0) red[warp] = mx;
    __syncthreads();
    if (tid < 32) {
        float t = (tid < 8) ? red[tid] : -1e30f;
        #pragma unroll
        for (int o = 4; o > 0; o >>= 1) t = fmaxf(t, __shfl_xor_sync(0xffffffffu, t, o));
        if (tid == 0) red[0] = t;
    }
    __syncthreads();
    mx = red[0];
    __syncthreads();

    float sum = 0.0f;
    for (int c = tid * 4; c < blockend; c += 1024) {
        float4 v = *(const float4*)&buf[c];
        float e0 = (c     < len) ? __expf(v.x - mx) : 0.0f;
        float e1 = (c + 1 < len) ? __expf(v.y - mx) : 0.0f;
        float e2 = (c + 2 < len) ? __expf(v.z - mx) : 0.0f;
        float e3 = (c + 3 < len) ? __expf(v.w - mx) : 0.0f;
        sum += (e0 + e1) + (e2 + e3);
        *(float4*)&buf[c] = make_float4(e0, e1, e2, e3);
    }
    #pragma unroll
    for (int o = 16; o > 0; o >>= 1) sum += __shfl_xor_sync(0xffffffffu, sum, o);
    if (lane == 0) red[warp] = sum;
    __syncthreads();
    if (tid < 32) {
        float t = (tid < 8) ? red[tid] : 0.0f;
        #pragma unroll
        for (int o = 4; o > 0; o >>= 1) t += __shfl_xor_sync(0xffffffffu, t, o);
        if (tid == 0) red[0] = t;
    }
    __syncthreads();
    float inv = 1.0f / red[0];

    for (int c = tid * 4; c < blockend; c += 1024) {
        float4 v = *(const float4*)&buf[c];
        v.x *= inv; v.y *= inv; v.z *= inv; v.w *= inv;
        *(float4*)&wrow[c] = v;
        uint32_t ph0, pl0, ph1, pl1;
        split2(v.x, v.y, ph0, pl0);
        split2(v.z, v.w, ph1, pl1);
        *(uint2*)&g_w_h[wb + c] = make_uint2(ph0, ph1);
        *(uint2*)&g_w_l[wb + c] = make_uint2(pl0, pl1);
    }
    for (int c = blockend + tid * 4; c < Sn; c += 1024)
        *(float4*)&wrow[c] = make_float4(0.f, 0.f, 0.f, 0.f);
}

// ---------------------------------------------------------------------------
// Kernel 4: attn_heads = weights @ V. block 128m x 64n, warp 64x16, causal.
// ---------------------------------------------------------------------------
__global__ __launch_bounds__(256, 2) void av_kernel() {
    extern __shared__ __align__(16) char dynsmem[];
    const uint32_t smb = s2u(dynsmem);
    int qb = gridDim.x - 1 - blockIdx.x;   // longest first
    int bh = blockIdx.y;
    int tid = threadIdx.x, lane = tid & 31, wid = tid >> 5;
    int row0 = qb * 128;
    int mbase = (wid & 1) * 64, nbase = (wid >> 1) * 16;
    int sar = tid >> 1, sah = (tid & 1) * 8;
    uint32_t a_off = (uint32_t)(sar * 24 + sah) * 2;
    int sbr = (tid & 127) >> 1, sbs = (tid & 1) * 8;
    uint32_t b_off = (uint32_t)(sbr * 24 + sbs) * 2;
    const __nv_bfloat16* gAh = g_w_h + (size_t)bh * Sn * Sn + (size_t)(row0 + sar) * Sn + sah;
    const __nv_bfloat16* gAl = g_w_l + (size_t)bh * Sn * Sn + (size_t)(row0 + sar) * Sn + sah;
    const __nv_bfloat16* gBh = g_v_h + ((size_t)bh * HDn + sbr) * Sn + sbs;
    const __nv_bfloat16* gBl = g_v_l + ((size_t)bh * HDn + sbr) * Sn + sbs;
    int a_row = lane & 15, a_colb = (lane >> 4) * 16;
    int b_row = (lane & 7) + ((lane >> 4) << 3);
    int b_colb = (lane & 8) ? 16 : 0;

    float acc[4][2][4] = {};
    const int T = (qb + 1) * 8;

    #define AISSUE(t) do { uint32_t st = smb + ((t) & 3) * STG_AV; \
        cpa16(st + a_off, gAh + (t) * 16); cpa16(st + 6144 + a_off, gAl + (t) * 16); \
        if (tid < 128) { cpa16(st + 12288 + b_off, gBh + (t) * 16); \
                         cpa16(st + 15360 + b_off, gBl + (t) * 16); } } while (0)

    for (int s = 0; s < STAGES - 1 && s < T; s++) { AISSUE(s); CP_COMMIT(); }
    for (int t = 0; t < T; t++) {
        CP_WAIT2();
        __syncthreads();
        if (t + STAGES - 1 < T) AISSUE(t + STAGES - 1);
        CP_COMMIT();
        cstage<2, 3072>(smb + (t & 3) * STG_AV, acc, mbase, nbase,
                        a_row, a_colb, b_row, b_colb);
    }
    #undef AISSUE

    #pragma unroll
    for (int i = 0; i < 4; i++) {
        #pragma unroll
        for (int j = 0; j < 2; j++) {
            int rr = row0 + mbase + i * 16 + (lane >> 2);
            int cc = nbase + j * 8 + (lane & 3) * 2;
            #pragma unroll
            for (int half = 0; half < 2; half++) {
                int r = rr + half * 8;
                uint32_t ph, pl;
                split2(acc[i][j][half * 2 + 0], acc[i][j][half * 2 + 1], ph, pl);
                size_t idx = ((size_t)bh * Sn + r) * HDn + cc;
                *(uint32_t*)&g_att_h[idx] = ph;
                *(uint32_t*)&g_att_l[idx] = pl;
            }
        }
    }
}

// ---------------------------------------------------------------------------
// Kernel 5: output projection, 128x128 tile, head-transpose in A staging.
// ---------------------------------------------------------------------------
__global__ __launch_bounds__(256, 2) void proj_gemm(const float* __restrict__ bias,
                                                    float* __restrict__ out) {
    extern __shared__ __align__(16) char dynsmem[];
    const uint32_t smb = s2u(dynsmem);
    const int K = 1024, N = 1024;
    int tid = threadIdx.x, lane = tid & 31, wid = tid >> 5;
    int row0 = blockIdx.y * 128, col0 = blockIdx.x * 128;
    int mbase = (wid & 1) * 64, nbase = (wid >> 1) * 32;
    int sar = tid >> 1, sah = (tid & 1) * 8;
    uint32_t a_off = (uint32_t)(sar * 24 + sah) * 2;
    uint32_t b_off = a_off;
    int arow = row0 + sar;
    int ab = arow >> 11, as = arow & 2047;
    size_t abase = ((size_t)ab * Hn * Sn + as) * HDn;
    const __nv_bfloat16* gBh = s_wp_h + (size_t)(col0 + sar) * K + sah;
    const __nv_bfloat16* gBl = s_wp_l + (size_t)(col0 + sar) * K + sah;
    int a_row = lane & 15, a_colb = (lane >> 4) * 16;
    int b_row = (lane & 7) + ((lane >> 4) << 3);
    int b_colb = (lane & 8) ? 16 : 0;

    float acc[4][4][4] = {};
    const int T = K / 16;

    #define PISSUE(t) do { uint32_t st = smb + ((t) & 3) * STG_W; \
        int c = (t) * 16 + sah; \
        size_t so = abase + (size_t)(c >> 6) * Sn * HDn + (c & 63); \
        cpa16(st + a_off, g_att_h + so); cpa16(st + 6144 + a_off, g_att_l + so); \
        cpa16(st + 12288 + b_off, gBh + (t) * 16); \
        cpa16(st + 18432 + b_off, gBl + (t) * 16); } while (0)

    for (int s = 0; s < STAGES - 1; s++) { PISSUE(s); CP_COMMIT(); }
    for (int t = 0; t < T; t++) {
        CP_WAIT2();
        __syncthreads();
        if (t + STAGES - 1 < T) PISSUE(t + STAGES - 1);
        CP_COMMIT();
        cstage<4, 6144>(smb + (t & 3) * STG_W, acc, mbase, nbase,
                        a_row, a_colb, b_row, b_colb);
    }
    #undef PISSUE

    #pragma unroll
    for (int i = 0; i < 4; i++) {
        #pragma unroll
        for (int j = 0; j < 4; j++) {
            int rr = row0 + mbase + i * 16 + (lane >> 2);
            int cc = col0 + nbase + j * 8 + (lane & 3) * 2;
            #pragma unroll
            for (int half = 0; half < 2; half++) {
                int r = rr + half * 8;
                out[(size_t)r * N + cc]     = acc[i][j][half * 2 + 0] + bias[cc];
                out[(size_t)r * N + cc + 1] = acc[i][j][half * 2 + 1] + bias[cc + 1];
            }
        }
    }
}

// ---------------------------------------------------------------------------
extern "C" void kernel_launch(void* const* d_in, const int* in_sizes, int n_in,
                              void* d_out, int out_size) {
    (void)in_sizes; (void)n_in; (void)out_size;
    const float* hs     = (const float*)d_in[0];
    const float* mask   = (const float*)d_in[1];
    const float* w_attn = (const float*)d_in[2];
    const float* b_attn = (const float*)d_in[3];
    const float* w_proj = (const float*)d_in[4];
    const float* b_proj = (const float*)d_in[5];

    float* attn_out = (float*)d_out;                          // [B,S,D]
    float* weights  = (float*)d_out + (size_t)Bn * Sn * Dn;   // [B,H,S,S]

    cudaFuncSetAttribute(qkv_gemm,      cudaFuncAttributeMaxDynamicSharedMemorySize, SMEM_W);
    cudaFuncSetAttribute(scores_kernel, cudaFuncAttributeMaxDynamicSharedMemorySize, SMEM_W);
    cudaFuncSetAttribute(av_kernel,     cudaFuncAttributeMaxDynamicSharedMemorySize, SMEM_AV);
    cudaFuncSetAttribute(proj_gemm,     cudaFuncAttributeMaxDynamicSharedMemorySize, SMEM_W);

    __nv_bfloat16 *wa_h, *wa_l, *wp_h, *wp_l;
    cudaGetSymbolAddress((void**)&wa_h, s_wa_h);
    cudaGetSymbolAddress((void**)&wa_l, s_wa_l);
    cudaGetSymbolAddress((void**)&wp_h, s_wp_h);
    cudaGetSymbolAddress((void**)&wp_l, s_wp_l);

    split_hs<<<BSn * Dn / 1024, 256>>>(hs);
    split_transpose<<<dim3(N3D / 32, Dn / 32), 256>>>(w_attn, wa_h, wa_l, Dn, N3D);
    split_transpose<<<dim3(Dn / 32, Dn / 32), 256>>>(w_proj, wp_h, wp_l, Dn, Dn);
    qkv_gemm<<<dim3(N3D / 128, BSn / 128), 256, SMEM_W>>>(b_attn);
    scores_kernel<<<dim3(136, Bn * Hn), 256, SMEM_W>>>(mask, weights);
    softmax_kernel<<<dim3(Bn * Hn * Sn), 256>>>(weights);
    av_kernel<<<dim3(Sn / 128, Bn * Hn), 256, SMEM_AV>>>();
    proj_gemm<<<dim3(Dn / 128, BSn / 128), 256, SMEM_W>>>(b_proj, attn_out);
}

// round 7
// speedup vs baseline: 2.5407x; 1.0336x over previous
#include <cuda_runtime.h>
#include <cuda_bf16.h>
#include <math.h>
#include <stdint.h>

#define Bn 2
#define Sn 2048
#define Dn 1024
#define Hn 16
#define HDn 64
#define BSn (Bn*Sn)      // 4096
#define N3D (3*Dn)       // 3072
#define NQKV (Bn*Hn*Sn*HDn)

// k32-stage slot layouts (128B rows, chunk-XOR swizzle, hi|lo packed per row):
//  wide (qkv/proj): A 128x128B (16KB) | B 128x128B (16KB) -> 32KB/slot
//  av:              A 16KB | B 64x128B (8KB)              -> 24KB/slot
#define SLOT_W  32768
#define SLOT_AV 24576
#define SMEM_W  (3*SLOT_W)    // 98304
#define SMEM_AV (3*SLOT_AV)   // 73728
// scores single-shot: Ah|Al|Bh|Bl regions of 16KB each
#define SMEM_SC 65536

// ---------------- bf16 hi/lo scratch (device globals) ----------------
__device__ __nv_bfloat16 s_hs_h[BSn*Dn],  s_hs_l[BSn*Dn];
__device__ __nv_bfloat16 s_wa_h[N3D*Dn],  s_wa_l[N3D*Dn];   // transposed [N][K]
__device__ __nv_bfloat16 s_wp_h[Dn*Dn],   s_wp_l[Dn*Dn];    // transposed [N][K]
__device__ __nv_bfloat16 g_q_h[NQKV], g_q_l[NQKV];          // [bh][s][hd]
__device__ __nv_bfloat16 g_k_h[NQKV], g_k_l[NQKV];          // [bh][s][hd]
__device__ __nv_bfloat16 g_v_h[NQKV], g_v_l[NQKV];          // [bh][hd][s] (transposed)
__device__ __nv_bfloat16 g_att_h[NQKV], g_att_l[NQKV];      // [bh][s][hd]
__device__ __nv_bfloat16 g_w_h[(size_t)Bn*Hn*Sn*Sn];
__device__ __nv_bfloat16 g_w_l[(size_t)Bn*Hn*Sn*Sn];

// ---------------- helpers ----------------
__device__ __forceinline__ uint32_t s2u(const void* p) {
    return (uint32_t)__cvta_generic_to_shared(p);
}
__device__ __forceinline__ void ldsm4(uint32_t& r0, uint32_t& r1, uint32_t& r2,
                                      uint32_t& r3, uint32_t a) {
    asm volatile("ldmatrix.sync.aligned.m8n8.x4.shared.b16 {%0,%1,%2,%3},[%4];"
                 : "=r"(r0), "=r"(r1), "=r"(r2), "=r"(r3) : "r"(a));
}
#define MMA(c, a, b) asm volatile( \
    "mma.sync.aligned.m16n8k16.row.col.f32.bf16.bf16.f32 " \
    "{%0,%1,%2,%3},{%4,%5,%6,%7},{%8,%9},{%0,%1,%2,%3};" \
    : "+f"((c)[0]), "+f"((c)[1]), "+f"((c)[2]), "+f"((c)[3]) \
    : "r"((a)[0]), "r"((a)[1]), "r"((a)[2]), "r"((a)[3]), "r"((b)[0]), "r"((b)[1]))

__device__ __forceinline__ void cpa16(uint32_t dst, const void* src) {
    asm volatile("cp.async.cg.shared.global [%0], [%1], 16;" :: "r"(dst), "l"(src));
}
#define CP_COMMIT() asm volatile("cp.async.commit_group;")
#define CP_WAIT1()  asm volatile("cp.async.wait_group 1;")
#define CP_WAIT0()  asm volatile("cp.async.wait_group 0;")

// byte offset of 16B chunk c in swizzled 128B row
__device__ __forceinline__ uint32_t swz(int row, int c) {
    return (uint32_t)row * 128u + (uint32_t)((c ^ (row & 7)) << 4);
}

__device__ __forceinline__ void split2(float x, float y, uint32_t& ph, uint32_t& pl) {
    uint32_t h;
    asm("cvt.rn.bf16x2.f32 %0, %1, %2;" : "=r"(h) : "f"(y), "f"(x));
    float hx = __uint_as_float(h << 16);
    float hy = __uint_as_float(h & 0xffff0000u);
    ph = h;
    asm("cvt.rn.bf16x2.f32 %0, %1, %2;" : "=r"(pl) : "f"(y - hy), "f"(x - hx));
}
__device__ __forceinline__ void split1(float x, __nv_bfloat16& h, __nv_bfloat16& l) {
    h = __float2bfloat16(x);
    l = __float2bfloat16(x - __bfloat162float(h));
}

// one k32 stage: A region at slot+0 (hi chunks 0-3, lo 4-7),
// B region at slot+16384 (hi 0-3, lo 4-7). 4 m-frags x NBF n-frags.
template<int NBF>
__device__ __forceinline__ void cstage32(uint32_t slot, float acc[4][NBF][4],
                                         int mbase, int nbase, int lane) {
    #pragma unroll
    for (int h = 0; h < 2; h++) {
        uint32_t bhf[NBF][2], blf[NBF][2];
        #pragma unroll
        for (int jg = 0; jg < NBF / 2; jg++) {
            int brow = nbase + jg * 16 + (lane & 7) + ((lane >> 4) << 3);
            int bch = h * 2 + ((lane >> 3) & 1);
            uint32_t r0, r1, r2, r3;
            ldsm4(r0, r1, r2, r3, slot + 16384u + swz(brow, bch));
            bhf[jg * 2][0] = r0; bhf[jg * 2][1] = r1;
            bhf[jg * 2 + 1][0] = r2; bhf[jg * 2 + 1][1] = r3;
            ldsm4(r0, r1, r2, r3, slot + 16384u + swz(brow, bch + 4));
            blf[jg * 2][0] = r0; blf[jg * 2][1] = r1;
            blf[jg * 2 + 1][0] = r2; blf[jg * 2 + 1][1] = r3;
        }
        #pragma unroll
        for (int i = 0; i < 4; i++) {
            int arow = mbase + i * 16 + (lane & 15);
            int ach = h * 2 + (lane >> 4);
            uint32_t ah[4], al[4];
            ldsm4(ah[0], ah[1], ah[2], ah[3], slot + swz(arow, ach));
            ldsm4(al[0], al[1], al[2], al[3], slot + swz(arow, ach + 4));
            #pragma unroll
            for (int j = 0; j < NBF; j++) {
                MMA(acc[i][j], ah, bhf[j]);
                MMA(acc[i][j], ah, blf[j]);
                MMA(acc[i][j], al, bhf[j]);
            }
        }
    }
}

// ---------------------------------------------------------------------------
// Kernel 0a/0b: input splits (unchanged).
// ---------------------------------------------------------------------------
__global__ __launch_bounds__(256) void split_hs(const float* __restrict__ hs) {
    int i = (blockIdx.x * 256 + threadIdx.x) * 4;
    float4 v = *(const float4*)&hs[i];
    uint32_t ph0, pl0, ph1, pl1;
    split2(v.x, v.y, ph0, pl0);
    split2(v.z, v.w, ph1, pl1);
    *(uint2*)&s_hs_h[i] = make_uint2(ph0, ph1);
    *(uint2*)&s_hs_l[i] = make_uint2(pl0, pl1);
}

__global__ __launch_bounds__(256) void split_transpose(const float* __restrict__ in,
                                                       __nv_bfloat16* __restrict__ oh,
                                                       __nv_bfloat16* __restrict__ ol,
                                                       int K, int N) {
    __shared__ float t[32][33];
    int nb = blockIdx.x * 32, kb = blockIdx.y * 32;
    int tx = threadIdx.x & 31, ty = threadIdx.x >> 5;
    #pragma unroll
    for (int i = 0; i < 4; i++) {
        int r = ty + i * 8;
        t[r][tx] = in[(size_t)(kb + r) * N + nb + tx];
    }
    __syncthreads();
    #pragma unroll
    for (int i = 0; i < 4; i++) {
        int r = ty + i * 8;
        float v = t[tx][r];
        __nv_bfloat16 h, l; split1(v, h, l);
        size_t o = (size_t)(nb + r) * K + kb + tx;
        oh[o] = h; ol[o] = l;
    }
}

// ---------------------------------------------------------------------------
// Kernel 1: QKV projection. 128m x 128n, warp 64x32, k32 x 32 stages.
// ---------------------------------------------------------------------------
__global__ __launch_bounds__(256, 2) void qkv_gemm(const float* __restrict__ bias) {
    extern __shared__ __align__(16) char dynsmem[];
    const uint32_t smb = s2u(dynsmem);
    const int K = 1024;
    int tid = threadIdx.x, lane = tid & 31, wid = tid >> 5;
    int row0 = blockIdx.y * 128, col0 = blockIdx.x * 128;
    int mbase = (wid & 1) * 64, nbase = (wid >> 1) * 32;
    int srow = tid >> 1, sh = tid & 1;
    const __nv_bfloat16* gAh = s_hs_h + (size_t)(row0 + srow) * K + sh * 16;
    const __nv_bfloat16* gAl = s_hs_l + (size_t)(row0 + srow) * K + sh * 16;
    const __nv_bfloat16* gBh = s_wa_h + (size_t)(col0 + srow) * K + sh * 16;
    const __nv_bfloat16* gBl = s_wa_l + (size_t)(col0 + srow) * K + sh * 16;
    uint32_t dA0 = swz(srow, sh * 2),     dA1 = swz(srow, sh * 2 + 1);
    uint32_t dL0 = swz(srow, sh * 2 + 4), dL1 = swz(srow, sh * 2 + 5);

    float acc[4][4][4] = {};
    const int T = K / 32;   // 32

    #define QISSUE(t) do { uint32_t sb = smb + ((t) % 3) * SLOT_W; \
        cpa16(sb + dA0, gAh + (t) * 32);      cpa16(sb + dA1, gAh + (t) * 32 + 8); \
        cpa16(sb + dL0, gAl + (t) * 32);      cpa16(sb + dL1, gAl + (t) * 32 + 8); \
        cpa16(sb + 16384 + dA0, gBh + (t) * 32); cpa16(sb + 16384 + dA1, gBh + (t) * 32 + 8); \
        cpa16(sb + 16384 + dL0, gBl + (t) * 32); cpa16(sb + 16384 + dL1, gBl + (t) * 32 + 8); } while (0)

    QISSUE(0); CP_COMMIT();
    QISSUE(1); CP_COMMIT();
    for (int t = 0; t < T; t++) {
        CP_WAIT1();
        __syncthreads();
        if (t + 2 < T) QISSUE(t + 2);
        CP_COMMIT();
        cstage32<4>(smb + (t % 3) * SLOT_W, acc, mbase, nbase, lane);
    }
    #undef QISSUE

    #pragma unroll
    for (int i = 0; i < 4; i++) {
        #pragma unroll
        for (int j = 0; j < 4; j++) {
            int rr = row0 + mbase + i * 16 + (lane >> 2);
            int cc = col0 + nbase + j * 8 + (lane & 3) * 2;
            #pragma unroll
            for (int half = 0; half < 2; half++) {
                int r = rr + half * 8;
                int b = r >> 11, s = r & 2047;
                float v0 = acc[i][j][half * 2 + 0] + bias[cc];
                float v1 = acc[i][j][half * 2 + 1] + bias[cc + 1];
                uint32_t ph, pl; split2(v0, v1, ph, pl);
                int which = cc >> 10;
                int dcol = cc & 1023;
                int h = dcol >> 6, hd = dcol & 63;
                int bh = b * Hn + h;
                if (which == 0) {
                    size_t idx = ((size_t)bh * Sn + s) * HDn + hd;
                    *(uint32_t*)&g_q_h[idx] = ph; *(uint32_t*)&g_q_l[idx] = pl;
                } else if (which == 1) {
                    size_t idx = ((size_t)bh * Sn + s) * HDn + hd;
                    *(uint32_t*)&g_k_h[idx] = ph; *(uint32_t*)&g_k_l[idx] = pl;
                } else {
                    size_t i0 = ((size_t)bh * HDn + hd) * Sn + s;
                    size_t i1 = ((size_t)bh * HDn + hd + 1) * Sn + s;
                    ((uint16_t*)g_v_h)[i0] = (uint16_t)(ph & 0xffff);
                    ((uint16_t*)g_v_h)[i1] = (uint16_t)(ph >> 16);
                    ((uint16_t*)g_v_l)[i0] = (uint16_t)(pl & 0xffff);
                    ((uint16_t*)g_v_l)[i1] = (uint16_t)(pl >> 16);
                }
            }
        }
    }
}

// ---------------------------------------------------------------------------
// Kernel 2: raw scores, lower-tri 128x128 tiles, K=64 loaded single-shot.
// smem: Ah 0 | Al 16384 | Bh 32768 | Bl 49152 (each 128 rows x 128B swizzled)
// ---------------------------------------------------------------------------
__global__ __launch_bounds__(256, 2) void scores_kernel(const float* __restrict__ mask,
                                                        float* __restrict__ Wout) {
    extern __shared__ __align__(16) char dynsmem[];
    const uint32_t smb = s2u(dynsmem);
    int idx = blockIdx.x;
    int qb = (int)((sqrtf(8.0f * idx + 1.0f) - 1.0f) * 0.5f);
    while ((qb + 1) * (qb + 2) / 2 <= idx) qb++;
    while (qb * (qb + 1) / 2 > idx) qb--;
    int kb = idx - qb * (qb + 1) / 2;
    int bh = blockIdx.y;
    int bb = bh >> 4;
    int tid = threadIdx.x, lane = tid & 31, wid = tid >> 5;
    int row0 = qb * 128, col0 = kb * 128;
    int mbase = (wid & 1) * 64, nbase = (wid >> 1) * 32;
    int srow = tid >> 1, sh = tid & 1;
    const __nv_bfloat16* gAh = g_q_h + ((size_t)bh * Sn + row0 + srow) * HDn + sh * 32;
    const __nv_bfloat16* gAl = g_q_l + ((size_t)bh * Sn + row0 + srow) * HDn + sh * 32;
    const __nv_bfloat16* gBh = g_k_h + ((size_t)bh * Sn + col0 + srow) * HDn + sh * 32;
    const __nv_bfloat16* gBl = g_k_l + ((size_t)bh * Sn + col0 + srow) * HDn + sh * 32;

    // single-shot load: 4 chunks per region per thread
    #pragma unroll
    for (int i = 0; i < 4; i++) {
        uint32_t d = swz(srow, sh * 4 + i);
        cpa16(smb + d,          gAh + i * 8);
        cpa16(smb + 16384 + d,  gAl + i * 8);
        cpa16(smb + 32768 + d,  gBh + i * 8);
        cpa16(smb + 49152 + d,  gBl + i * 8);
    }
    CP_COMMIT();
    CP_WAIT0();
    __syncthreads();

    float acc[4][4][4] = {};
    #pragma unroll
    for (int h = 0; h < 4; h++) {
        uint32_t bhf[4][2], blf[4][2];
        #pragma unroll
        for (int jg = 0; jg < 2; jg++) {
            int brow = nbase + jg * 16 + (lane & 7) + ((lane >> 4) << 3);
            int bch = h * 2 + ((lane >> 3) & 1);
            uint32_t r0, r1, r2, r3;
            ldsm4(r0, r1, r2, r3, smb + 32768u + swz(brow, bch));
            bhf[jg * 2][0] = r0; bhf[jg * 2][1] = r1;
            bhf[jg * 2 + 1][0] = r2; bhf[jg * 2 + 1][1] = r3;
            ldsm4(r0, r1, r2, r3, smb + 49152u + swz(brow, bch));
            blf[jg * 2][0] = r0; blf[jg * 2][1] = r1;
            blf[jg * 2 + 1][0] = r2; blf[jg * 2 + 1][1] = r3;
        }
        #pragma unroll
        for (int i = 0; i < 4; i++) {
            int arow = mbase + i * 16 + (lane & 15);
            int ach = h * 2 + (lane >> 4);
            uint32_t ah[4], al[4];
            ldsm4(ah[0], ah[1], ah[2], ah[3], smb + swz(arow, ach));
            ldsm4(al[0], al[1], al[2], al[3], smb + 16384u + swz(arow, ach));
            #pragma unroll
            for (int j = 0; j < 4; j++) {
                MMA(acc[i][j], ah, bhf[j]);
                MMA(acc[i][j], ah, blf[j]);
                MMA(acc[i][j], al, bhf[j]);
            }
        }
    }

    const float scale = 0.125f;
    #pragma unroll
    for (int i = 0; i < 4; i++) {
        #pragma unroll
        for (int j = 0; j < 4; j++) {
            int rr = row0 + mbase + i * 16 + (lane >> 2);
            int cc = col0 + nbase + j * 8 + (lane & 3) * 2;
            #pragma unroll
            for (int half = 0; half < 2; half++) {
                int r = rr + half * 8;
                float* orow = Wout + ((size_t)bh * Sn + r) * Sn;
                orow[cc]     = acc[i][j][half * 2 + 0] * scale + mask[bb * Sn + cc];
                orow[cc + 1] = acc[i][j][half * 2 + 1] * scale + mask[bb * Sn + cc + 1];
            }
        }
    }
}

// ---------------------------------------------------------------------------
// Kernel 3: row softmax (unchanged from R5).
// ---------------------------------------------------------------------------
__global__ __launch_bounds__(256) void softmax_kernel(float* __restrict__ Wm) {
    __shared__ float buf[Sn];
    __shared__ float red[8];
    int row = blockIdx.x;
    int q = row & (Sn - 1);
    int len = q + 1;
    int blockend = ((q >> 7) + 1) << 7;
    float* wrow = Wm + (size_t)row * Sn;
    size_t wb = (size_t)row * Sn;
    int tid = threadIdx.x;
    int lane = tid & 31, warp = tid >> 5;

    float mx = -1e30f;
    for (int c = tid * 4; c < blockend; c += 1024) {
        float4 v = *(const float4*)&wrow[c];
        *(float4*)&buf[c] = v;
        if (c + 3 < len) {
            mx = fmaxf(mx, fmaxf(fmaxf(v.x, v.y), fmaxf(v.z, v.w)));
        } else {
            if (c     < len) mx = fmaxf(mx, v.x);
            if (c + 1 < len) mx = fmaxf(mx, v.y);
            if (c + 2 < len) mx = fmaxf(mx, v.z);
            if (c + 3 < len) mx = fmaxf(mx, v.w);
        }
    }
    #pragma unroll
    for (int o = 16; o > 0; o >>= 1) mx = fmaxf(mx, __shfl_xor_sync(0xffffffffu, mx, o));
    if (lane == 0) red[warp] = mx;
    __syncthreads();
    if (tid < 32) {
        float t = (tid < 8) ? red[tid] : -1e30f;
        #pragma unroll
        for (int o = 4; o > 0; o >>= 1) t = fmaxf(t, __shfl_xor_sync(0xffffffffu, t, o));
        if (tid == 0) red[0] = t;
    }
    __syncthreads();
    mx = red[0];
    __syncthreads();

    float sum = 0.0f;
    for (int c = tid * 4; c < blockend; c += 1024) {
        float4 v = *(const float4*)&buf[c];
        float e0 = (c     < len) ? __expf(v.x - mx) : 0.0f;
        float e1 = (c + 1 < len) ? __expf(v.y - mx) : 0.0f;
        float e2 = (c + 2 < len) ? __expf(v.z - mx) : 0.0f;
        float e3 = (c + 3 < len) ? __expf(v.w - mx) : 0.0f;
        sum += (e0 + e1) + (e2 + e3);
        *(float4*)&buf[c] = make_float4(e0, e1, e2, e3);
    }
    #pragma unroll
    for (int o = 16; o > 0; o >>= 1) sum += __shfl_xor_sync(0xffffffffu, sum, o);
    if (lane == 0) red[warp] = sum;
    __syncthreads();
    if (tid < 32) {
        float t = (tid < 8) ? red[tid] : 0.0f;
        #pragma unroll
        for (int o = 4; o > 0; o >>= 1) t += __shfl_xor_sync(0xffffffffu, t, o);
        if (tid == 0) red[0] = t;
    }
    __syncthreads();
    float inv = 1.0f / red[0];

    for (int c = tid * 4; c < blockend; c += 1024) {
        float4 v = *(const float4*)&buf[c];
        v.x *= inv; v.y *= inv; v.z *= inv; v.w *= inv;
        *(float4*)&wrow[c] = v;
        uint32_t ph0, pl0, ph1, pl1;
        split2(v.x, v.y, ph0, pl0);
        split2(v.z, v.w, ph1, pl1);
        *(uint2*)&g_w_h[wb + c] = make_uint2(ph0, ph1);
        *(uint2*)&g_w_l[wb + c] = make_uint2(pl0, pl1);
    }
    for (int c = blockend + tid * 4; c < Sn; c += 1024)
        *(float4*)&wrow[c] = make_float4(0.f, 0.f, 0.f, 0.f);
}

// ---------------------------------------------------------------------------
// Kernel 4: attn_heads = weights @ V. 128m x 64n, warp 64x16, k32 stages.
// ---------------------------------------------------------------------------
__global__ __launch_bounds__(256, 2) void av_kernel() {
    extern __shared__ __align__(16) char dynsmem[];
    const uint32_t smb = s2u(dynsmem);
    int qb = gridDim.x - 1 - blockIdx.x;   // longest first
    int bh = blockIdx.y;
    int tid = threadIdx.x, lane = tid & 31, wid = tid >> 5;
    int row0 = qb * 128;
    int mbase = (wid & 1) * 64, nbase = (wid >> 1) * 16;
    int srow = tid >> 1, sh = tid & 1;
    const __nv_bfloat16* gAh = g_w_h + (size_t)bh * Sn * Sn + (size_t)(row0 + srow) * Sn + sh * 16;
    const __nv_bfloat16* gAl = g_w_l + (size_t)bh * Sn * Sn + (size_t)(row0 + srow) * Sn + sh * 16;
    const __nv_bfloat16* gBh = g_v_h + ((size_t)bh * HDn + srow) * Sn + sh * 16;  // tid<128
    const __nv_bfloat16* gBl = g_v_l + ((size_t)bh * HDn + srow) * Sn + sh * 16;
    uint32_t dA0 = swz(srow, sh * 2),     dA1 = swz(srow, sh * 2 + 1);
    uint32_t dL0 = swz(srow, sh * 2 + 4), dL1 = swz(srow, sh * 2 + 5);

    float acc[4][2][4] = {};
    const int T = (qb + 1) * 4;

    #define AISSUE(t) do { uint32_t sb = smb + ((t) % 3) * SLOT_AV; \
        cpa16(sb + dA0, gAh + (t) * 32);      cpa16(sb + dA1, gAh + (t) * 32 + 8); \
        cpa16(sb + dL0, gAl + (t) * 32);      cpa16(sb + dL1, gAl + (t) * 32 + 8); \
        if (tid < 128) { \
            cpa16(sb + 16384 + dA0, gBh + (t) * 32); cpa16(sb + 16384 + dA1, gBh + (t) * 32 + 8); \
            cpa16(sb + 16384 + dL0, gBl + (t) * 32); cpa16(sb + 16384 + dL1, gBl + (t) * 32 + 8); } } while (0)

    AISSUE(0); CP_COMMIT();
    AISSUE(1); CP_COMMIT();
    for (int t = 0; t < T; t++) {
        CP_WAIT1();
        __syncthreads();
        if (t + 2 < T) AISSUE(t + 2);
        CP_COMMIT();
        cstage32<2>(smb + (t % 3) * SLOT_AV, acc, mbase, nbase, lane);
    }
    #undef AISSUE

    #pragma unroll
    for (int i = 0; i < 4; i++) {
        #pragma unroll
        for (int j = 0; j < 2; j++) {
            int rr = row0 + mbase + i * 16 + (lane >> 2);
            int cc = nbase + j * 8 + (lane & 3) * 2;
            #pragma unroll
            for (int half = 0; half < 2; half++) {
                int r = rr + half * 8;
                uint32_t ph, pl;
                split2(acc[i][j][half * 2 + 0], acc[i][j][half * 2 + 1], ph, pl);
                size_t idx = ((size_t)bh * Sn + r) * HDn + cc;
                *(uint32_t*)&g_att_h[idx] = ph;
                *(uint32_t*)&g_att_l[idx] = pl;
            }
        }
    }
}

// ---------------------------------------------------------------------------
// Kernel 5: output projection, 128x128 tile, k32 stages, head-transpose in A.
// ---------------------------------------------------------------------------
__global__ __launch_bounds__(256, 2) void proj_gemm(const float* __restrict__ bias,
                                                    float* __restrict__ out) {
    extern __shared__ __align__(16) char dynsmem[];
    const uint32_t smb = s2u(dynsmem);
    const int K = 1024, N = 1024;
    int tid = threadIdx.x, lane = tid & 31, wid = tid >> 5;
    int row0 = blockIdx.y * 128, col0 = blockIdx.x * 128;
    int mbase = (wid & 1) * 64, nbase = (wid >> 1) * 32;
    int srow = tid >> 1, sh = tid & 1;
    int arow = row0 + srow;
    int ab = arow >> 11, as = arow & 2047;
    size_t abase = (((size_t)ab * Hn) * Sn + as) * HDn;  // + head*Sn*HDn + hd
    const __nv_bfloat16* gBh = s_wp_h + (size_t)(col0 + srow) * K + sh * 16;
    const __nv_bfloat16* gBl = s_wp_l + (size_t)(col0 + srow) * K + sh * 16;
    uint32_t dA0 = swz(srow, sh * 2),     dA1 = swz(srow, sh * 2 + 1);
    uint32_t dL0 = swz(srow, sh * 2 + 4), dL1 = swz(srow, sh * 2 + 5);

    float acc[4][4][4] = {};
    const int T = K / 32;   // 32; stage t covers head t>>1, hd half (t&1)*32

    #define PISSUE(t) do { uint32_t sb = smb + ((t) % 3) * SLOT_W; \
        size_t so = abase + (size_t)((t) >> 1) * Sn * HDn + ((t) & 1) * 32 + sh * 16; \
        cpa16(sb + dA0, g_att_h + so);      cpa16(sb + dA1, g_att_h + so + 8); \
        cpa16(sb + dL0, g_att_l + so);      cpa16(sb + dL1, g_att_l + so + 8); \
        cpa16(sb + 16384 + dA0, gBh + (t) * 32); cpa16(sb + 16384 + dA1, gBh + (t) * 32 + 8); \
        cpa16(sb + 16384 + dL0, gBl + (t) * 32); cpa16(sb + 16384 + dL1, gBl + (t) * 32 + 8); } while (0)

    PISSUE(0); CP_COMMIT();
    PISSUE(1); CP_COMMIT();
    for (int t = 0; t < T; t++) {
        CP_WAIT1();
        __syncthreads();
        if (t + 2 < T) PISSUE(t + 2);
        CP_COMMIT();
        cstage32<4>(smb + (t % 3) * SLOT_W, acc, mbase, nbase, lane);
    }
    #undef PISSUE

    #pragma unroll
    for (int i = 0; i < 4; i++) {
        #pragma unroll
        for (int j = 0; j < 4; j++) {
            int rr = row0 + mbase + i * 16 + (lane >> 2);
            int cc = col0 + nbase + j * 8 + (lane & 3) * 2;
            #pragma unroll
            for (int half = 0; half < 2; half++) {
                int r = rr + half * 8;
                out[(size_t)r * N + cc]     = acc[i][j][half * 2 + 0] + bias[cc];
                out[(size_t)r * N + cc + 1] = acc[i][j][half * 2 + 1] + bias[cc + 1];
            }
        }
    }
}

// ---------------------------------------------------------------------------
extern "C" void kernel_launch(void* const* d_in, const int* in_sizes, int n_in,
                              void* d_out, int out_size) {
    (void)in_sizes; (void)n_in; (void)out_size;
    const float* hs     = (const float*)d_in[0];
    const float* mask   = (const float*)d_in[1];
    const float* w_attn = (const float*)d_in[2];
    const float* b_attn = (const float*)d_in[3];
    const float* w_proj = (const float*)d_in[4];
    const float* b_proj = (const float*)d_in[5];

    float* attn_out = (float*)d_out;                          // [B,S,D]
    float* weights  = (float*)d_out + (size_t)Bn * Sn * Dn;   // [B,H,S,S]

    cudaFuncSetAttribute(qkv_gemm,      cudaFuncAttributeMaxDynamicSharedMemorySize, SMEM_W);
    cudaFuncSetAttribute(scores_kernel, cudaFuncAttributeMaxDynamicSharedMemorySize, SMEM_SC);
    cudaFuncSetAttribute(av_kernel,     cudaFuncAttributeMaxDynamicSharedMemorySize, SMEM_AV);
    cudaFuncSetAttribute(proj_gemm,     cudaFuncAttributeMaxDynamicSharedMemorySize, SMEM_W);

    __nv_bfloat16 *wa_h, *wa_l, *wp_h, *wp_l;
    cudaGetSymbolAddress((void**)&wa_h, s_wa_h);
    cudaGetSymbolAddress((void**)&wa_l, s_wa_l);
    cudaGetSymbolAddress((void**)&wp_h, s_wp_h);
    cudaGetSymbolAddress((void**)&wp_l, s_wp_l);

    split_hs<<<BSn * Dn / 1024, 256>>>(hs);
    split_transpose<<<dim3(N3D / 32, Dn / 32), 256>>>(w_attn, wa_h, wa_l, Dn, N3D);
    split_transpose<<<dim3(Dn / 32, Dn / 32), 256>>>(w_proj, wp_h, wp_l, Dn, Dn);
    qkv_gemm<<<dim3(N3D / 128, BSn / 128), 256, SMEM_W>>>(b_attn);
    scores_kernel<<<dim3(136, Bn * Hn), 256, SMEM_SC>>>(mask, weights);
    softmax_kernel<<<dim3(Bn * Hn * Sn), 256>>>(weights);
    av_kernel<<<dim3(Sn / 128, Bn * Hn), 256, SMEM_AV>>>();
    proj_gemm<<<dim3(Dn / 128, BSn / 128), 256, SMEM_W>>>(b_proj, attn_out);
}